// round 1
// baseline (speedup 1.0000x reference)
#include <cuda_runtime.h>
#include <math.h>

#define BB   4
#define SS   2048
#define HID  1024
#define NH   16
#define HD   64
#define ROWS (BB*SS)
#define SCALE 0.125f   // 1/sqrt(64)

// Scratch (alloc-free rule: __device__ globals)
__device__ float g_Q[ROWS * HID];
__device__ float g_K[ROWS * HID];
__device__ float g_V[ROWS * HID];
__device__ float g_AO[ROWS * HID];

// ---------------------------------------------------------------------------
// SGEMM: C[M=8192, N=1024] = A[M,K=1024] @ W[K,N], row-major fp32.
// 128x128 block tile, BK=16, 256 threads, 8x8 micro-tile per thread.
// MASK=1: zero rows whose seq position >= seq_lens[batch] (for the Wo output).
// ---------------------------------------------------------------------------
template <int MASK>
__global__ __launch_bounds__(256) void sgemm_kernel(
    const float* __restrict__ A, const float* __restrict__ W,
    float* __restrict__ C, const int* __restrict__ seq_lens)
{
    const int K = HID, N = HID;
    __shared__ __align__(16) float As[16][128];   // [k][m] transposed
    __shared__ __align__(16) float Ws[16][128];   // [k][n]

    const int t  = threadIdx.x;
    const int bm = blockIdx.y * 128;
    const int bn = blockIdx.x * 128;
    const int ty = t >> 4;     // 0..15 -> rows ty*8..+7
    const int tx = t & 15;     // 0..15 -> cols tx*8..+7

    float acc[8][8];
#pragma unroll
    for (int i = 0; i < 8; i++)
#pragma unroll
        for (int j = 0; j < 8; j++) acc[i][j] = 0.f;

    const float* Ab = A + (long)bm * K;
    const float* Wb = W + bn;

    for (int kt = 0; kt < K; kt += 16) {
        // Load A tile 128x16 (2 float4 per thread), store transposed
#pragma unroll
        for (int r = 0; r < 2; r++) {
            int lin = t + r * 256;            // 0..511
            int row = lin >> 2;               // 0..127
            int kk  = (lin & 3) * 4;          // 0,4,8,12
            float4 v = *(const float4*)(Ab + (long)row * K + kt + kk);
            As[kk + 0][row] = v.x; As[kk + 1][row] = v.y;
            As[kk + 2][row] = v.z; As[kk + 3][row] = v.w;
        }
        // Load W tile 16x128 (2 float4 per thread)
#pragma unroll
        for (int r = 0; r < 2; r++) {
            int lin = t + r * 256;            // 0..511
            int kr = lin >> 5;                // 0..15
            int nc = (lin & 31) * 4;          // 0..124
            *(float4*)&Ws[kr][nc] = *(const float4*)(Wb + (long)(kt + kr) * N + nc);
        }
        __syncthreads();

#pragma unroll
        for (int k = 0; k < 16; k++) {
            float a[8], b[8];
            *(float4*)&a[0] = *(const float4*)&As[k][ty * 8];
            *(float4*)&a[4] = *(const float4*)&As[k][ty * 8 + 4];
            *(float4*)&b[0] = *(const float4*)&Ws[k][tx * 8];
            *(float4*)&b[4] = *(const float4*)&Ws[k][tx * 8 + 4];
#pragma unroll
            for (int i = 0; i < 8; i++)
#pragma unroll
                for (int j = 0; j < 8; j++)
                    acc[i][j] = fmaf(a[i], b[j], acc[i][j]);
        }
        __syncthreads();
    }

#pragma unroll
    for (int i = 0; i < 8; i++) {
        int row = bm + ty * 8 + i;
        bool valid = true;
        if (MASK) {
            int s  = row & (SS - 1);
            int bb = row >> 11;               // row / 2048
            valid = s < __ldg(&seq_lens[bb]);
        }
#pragma unroll
        for (int j4 = 0; j4 < 2; j4++) {
            float4 v;
            if (valid) {
                v.x = acc[i][j4 * 4 + 0]; v.y = acc[i][j4 * 4 + 1];
                v.z = acc[i][j4 * 4 + 2]; v.w = acc[i][j4 * 4 + 3];
            } else {
                v = make_float4(0.f, 0.f, 0.f, 0.f);
            }
            *(float4*)(C + (long)row * N + bn + tx * 8 + j4 * 4) = v;
        }
    }
}

// ---------------------------------------------------------------------------
// RoPE in-place on a [ROWS, NH*HD] tensor. Each thread handles one (row,h,j)
// pair rotating (j, j+32) within the 64-wide head.
// ---------------------------------------------------------------------------
__global__ __launch_bounds__(256) void rope_kernel(float* __restrict__ P)
{
    int idx = blockIdx.x * blockDim.x + threadIdx.x;
    if (idx >= ROWS * NH * 32) return;
    int j   = idx & 31;
    int h   = (idx >> 5) & (NH - 1);
    int row = idx >> 9;
    int s   = row & (SS - 1);

    // inv_freq = 10000^(-j/32) = exp(-j * ln(10000)/32)
    float inv = expf(-(float)j * (9.210340371976184f / 32.0f));
    float ang = (float)s * inv;
    float sn, cs;
    sincosf(ang, &sn, &cs);

    long base = (long)row * HID + h * HD + j;
    float x1 = P[base];
    float x2 = P[base + 32];
    P[base]      = x1 * cs - x2 * sn;
    P[base + 32] = x2 * cs + x1 * sn;
}

// ---------------------------------------------------------------------------
// Flash attention, fp32, causal, 64x64 tiles, online softmax.
// Grid: (S/64, NH, B). 256 threads; thread (ty,tx) owns 4 rows x 4 cols.
// Skips q-tiles entirely beyond seq_len (writes zeros) and k-tiles beyond the
// causal diagonal.
// ---------------------------------------------------------------------------
__global__ __launch_bounds__(256) void flash_kernel(
    const float* __restrict__ Q, const float* __restrict__ K,
    const float* __restrict__ V, float* __restrict__ AO,
    const int* __restrict__ seq_lens)
{
    const int PAD = 65;
    extern __shared__ float sm[];
    float* Qs = sm;                  // 64*PAD
    float* Ks = Qs + 64 * PAD;
    float* Vs = Ks + 64 * PAD;
    float* Ps = Vs + 64 * PAD;

    const int qt = blockIdx.x, h = blockIdx.y, b = blockIdx.z;
    const int sl = __ldg(&seq_lens[b]);
    const int q0 = qt * 64;
    const int t  = threadIdx.x;
    const int ty = t >> 4;   // row group: rows ty*4..+3
    const int tx = t & 15;   // col group: cols tx*4..+3

    const long base = (long)b * SS * HID + (long)h * HD;

    if (q0 >= sl) {
        // Entire tile is past the valid length: output zeros.
        for (int lin = t; lin < 64 * 16; lin += 256) {
            int r = lin >> 4, c4 = (lin & 15) * 4;
            *(float4*)(AO + base + (long)(q0 + r) * HID + c4) =
                make_float4(0.f, 0.f, 0.f, 0.f);
        }
        return;
    }

    // Load Q tile
    for (int lin = t; lin < 64 * 16; lin += 256) {
        int r = lin >> 4, c4 = (lin & 15) * 4;
        float4 v = *(const float4*)(Q + base + (long)(q0 + r) * HID + c4);
        float* d = &Qs[r * PAD + c4];
        d[0] = v.x; d[1] = v.y; d[2] = v.z; d[3] = v.w;
    }

    float m_i[4], l_i[4], o[4][4];
#pragma unroll
    for (int i = 0; i < 4; i++) {
        m_i[i] = -1e30f; l_i[i] = 0.f;
#pragma unroll
        for (int j = 0; j < 4; j++) o[i][j] = 0.f;
    }
    __syncthreads();

    for (int kt = 0; kt <= qt; kt++) {
        const int k0 = kt * 64;
        // Load K and V tiles
        for (int lin = t; lin < 64 * 16; lin += 256) {
            int r = lin >> 4, c4 = (lin & 15) * 4;
            long off = base + (long)(k0 + r) * HID + c4;
            float4 kv = *(const float4*)(K + off);
            float4 vv = *(const float4*)(V + off);
            float* dk = &Ks[r * PAD + c4];
            dk[0] = kv.x; dk[1] = kv.y; dk[2] = kv.z; dk[3] = kv.w;
            float* dv = &Vs[r * PAD + c4];
            dv[0] = vv.x; dv[1] = vv.y; dv[2] = vv.z; dv[3] = vv.w;
        }
        __syncthreads();

        // S = Q K^T (4x4 micro-tile)
        float s_acc[4][4];
#pragma unroll
        for (int i = 0; i < 4; i++)
#pragma unroll
            for (int j = 0; j < 4; j++) s_acc[i][j] = 0.f;

#pragma unroll 8
        for (int dd = 0; dd < 64; dd++) {
            float qv[4], kv[4];
#pragma unroll
            for (int i = 0; i < 4; i++) qv[i] = Qs[(ty * 4 + i) * PAD + dd];
#pragma unroll
            for (int j = 0; j < 4; j++) kv[j] = Ks[(tx * 4 + j) * PAD + dd];
#pragma unroll
            for (int i = 0; i < 4; i++)
#pragma unroll
                for (int j = 0; j < 4; j++)
                    s_acc[i][j] = fmaf(qv[i], kv[j], s_acc[i][j]);
        }

        const bool diag = (kt == qt);
        // Online softmax per row
#pragma unroll
        for (int i = 0; i < 4; i++) {
            int qg = q0 + ty * 4 + i;
            float mloc = -1e30f;
#pragma unroll
            for (int j = 0; j < 4; j++) {
                float sv = s_acc[i][j] * SCALE;
                if (diag && (k0 + tx * 4 + j) > qg) sv = -1e30f;
                s_acc[i][j] = sv;
                mloc = fmaxf(mloc, sv);
            }
#pragma unroll
            for (int ofs = 8; ofs >= 1; ofs >>= 1)
                mloc = fmaxf(mloc, __shfl_xor_sync(0xffffffffu, mloc, ofs, 16));
            float mnew = fmaxf(m_i[i], mloc);
            float corr = __expf(m_i[i] - mnew);
            m_i[i] = mnew;
            float psum = 0.f;
#pragma unroll
            for (int j = 0; j < 4; j++) {
                float p = __expf(s_acc[i][j] - mnew);
                s_acc[i][j] = p;
                psum += p;
            }
#pragma unroll
            for (int ofs = 8; ofs >= 1; ofs >>= 1)
                psum += __shfl_xor_sync(0xffffffffu, psum, ofs, 16);
            l_i[i] = l_i[i] * corr + psum;
#pragma unroll
            for (int j = 0; j < 4; j++) {
                o[i][j] *= corr;
                Ps[(ty * 4 + i) * PAD + tx * 4 + j] = s_acc[i][j];
            }
        }
        __syncthreads();

        // O += P @ V
#pragma unroll 8
        for (int kk = 0; kk < 64; kk++) {
            float pv[4], vv[4];
#pragma unroll
            for (int i = 0; i < 4; i++) pv[i] = Ps[(ty * 4 + i) * PAD + kk];
#pragma unroll
            for (int j = 0; j < 4; j++) vv[j] = Vs[kk * PAD + tx * 4 + j];
#pragma unroll
            for (int i = 0; i < 4; i++)
#pragma unroll
                for (int j = 0; j < 4; j++)
                    o[i][j] = fmaf(pv[i], vv[j], o[i][j]);
        }
        __syncthreads();
    }

    // Store O / l, zeroing rows past seq_len
#pragma unroll
    for (int i = 0; i < 4; i++) {
        int r = ty * 4 + i;
        bool valid = (q0 + r) < sl;
        float invl = valid ? (1.f / l_i[i]) : 0.f;
#pragma unroll
        for (int j = 0; j < 4; j++)
            AO[base + (long)(q0 + r) * HID + tx * 4 + j] = o[i][j] * invl;
    }
}

// ---------------------------------------------------------------------------
extern "C" void kernel_launch(void* const* d_in, const int* in_sizes, int n_in,
                              void* d_out, int out_size)
{
    (void)in_sizes; (void)n_in; (void)out_size;
    const float* x  = (const float*)d_in[0];
    const float* Wq = (const float*)d_in[1];
    const float* Wk = (const float*)d_in[2];
    const float* Wv = (const float*)d_in[3];
    const float* Wo = (const float*)d_in[4];
    const int*   sl = (const int*)d_in[5];
    float* out = (float*)d_out;

    float *Q, *K, *V, *AO;
    cudaGetSymbolAddress((void**)&Q,  g_Q);
    cudaGetSymbolAddress((void**)&K,  g_K);
    cudaGetSymbolAddress((void**)&V,  g_V);
    cudaGetSymbolAddress((void**)&AO, g_AO);

    const int FLASH_SMEM = 4 * 64 * 65 * (int)sizeof(float);  // 66560 B
    cudaFuncSetAttribute(flash_kernel,
                         cudaFuncAttributeMaxDynamicSharedMemorySize, FLASH_SMEM);

    dim3 gemm_grid(HID / 128, ROWS / 128);   // (8, 64)
    sgemm_kernel<0><<<gemm_grid, 256>>>(x, Wq, Q, nullptr);
    sgemm_kernel<0><<<gemm_grid, 256>>>(x, Wk, K, nullptr);
    sgemm_kernel<0><<<gemm_grid, 256>>>(x, Wv, V, nullptr);

    int rope_n = ROWS * NH * 32;
    rope_kernel<<<rope_n / 256, 256>>>(Q);
    rope_kernel<<<rope_n / 256, 256>>>(K);

    dim3 flash_grid(SS / 64, NH, BB);        // (32, 16, 4)
    flash_kernel<<<flash_grid, 256, FLASH_SMEM>>>(Q, K, V, AO, sl);

    sgemm_kernel<1><<<gemm_grid, 256>>>(AO, Wo, out, sl);
}

// round 3
// speedup vs baseline: 1.3246x; 1.3246x over previous
#include <cuda_runtime.h>
#include <mma.h>
#include <cstdint>
#include <math.h>

using namespace nvcuda;

#define BB   4
#define SS   2048
#define HID  1024
#define NH   16
#define HD   64
#define ROWS (BB*SS)
#define SCALE 0.125f   // 1/sqrt(64)

// Scratch (alloc-free rule: __device__ globals)
__device__ float g_Q[ROWS * HID];
__device__ float g_K[ROWS * HID];
__device__ float g_V[ROWS * HID];
__device__ float g_AO[ROWS * HID];
__device__ float g_Wt[4 * HID * HID];   // transposed weights: Wt[n][k] = W[k][n]

// ---------------------------------------------------------------------------
// Weight transpose: Wt[z][n][k] = W_z[k][n], 1024x1024 each.
// ---------------------------------------------------------------------------
__global__ __launch_bounds__(256) void transpose_kernel(
    const float* __restrict__ W0, const float* __restrict__ W1,
    const float* __restrict__ W2, const float* __restrict__ W3)
{
    __shared__ float tile[32][33];
    const int z = blockIdx.z;
    const float* W = (z == 0) ? W0 : (z == 1) ? W1 : (z == 2) ? W2 : W3;
    float* T = g_Wt + (size_t)z * HID * HID;
    const int k0 = blockIdx.x * 32, n0 = blockIdx.y * 32;
    const int tx = threadIdx.x & 31, ty = threadIdx.x >> 5;   // 32 x 8
#pragma unroll
    for (int r = 0; r < 4; r++)
        tile[ty + r * 8][tx] = W[(size_t)(k0 + ty + r * 8) * HID + n0 + tx];
    __syncthreads();
#pragma unroll
    for (int r = 0; r < 4; r++)
        T[(size_t)(n0 + ty + r * 8) * HID + k0 + tx] = tile[tx][ty + r * 8];
}

// ---------------------------------------------------------------------------
// WMMA tf32 GEMM: C[8192,1024] = A[8192,1024] @ Bt^T
//   Bt is [N=1024, K=1024] (K contiguous) = pre-transposed weight.
// Block tile 128x128, BK=32, 256 threads (8 warps), warp tile 64x32.
// A row_major fragments; B col_major fragments map exactly onto Bt's [n][k]
// layout (element (k,n) at n*ld + k).
// ---------------------------------------------------------------------------
#define BK   32
#define LDS_PAD 40   // 32 + 8 floats padding

__global__ __launch_bounds__(256) void wgemm_kernel(
    const float* __restrict__ A, const float* __restrict__ Bt,
    float* __restrict__ C)
{
    __shared__ float As[128][LDS_PAD];
    __shared__ float Bs[128][LDS_PAD];

    const int t   = threadIdx.x;
    const int wid = t >> 5;
    const int bm  = blockIdx.y * 128;
    const int bn  = blockIdx.x * 128;
    const int wm  = wid & 1;     // 0..1 -> 64-row strip
    const int wn  = wid >> 1;    // 0..3 -> 32-col strip

    wmma::fragment<wmma::accumulator, 16, 16, 8, float> acc[4][2];
#pragma unroll
    for (int mi = 0; mi < 4; mi++)
#pragma unroll
        for (int ni = 0; ni < 2; ni++)
            wmma::fill_fragment(acc[mi][ni], 0.0f);

    for (int kt = 0; kt < HID; kt += BK) {
        // Load 128x32 tiles of A and Bt (4 float4 per matrix per thread)
#pragma unroll
        for (int it = 0; it < 4; it++) {
            int lin = t + it * 256;           // 0..1023
            int row = lin >> 3;               // 0..127
            int kq  = (lin & 7) * 4;          // 0,4,...,28
            float4 va = *(const float4*)(A  + (size_t)(bm + row) * HID + kt + kq);
            float4 vb = *(const float4*)(Bt + (size_t)(bn + row) * HID + kt + kq);
            As[row][kq + 0] = wmma::__float_to_tf32(va.x);
            As[row][kq + 1] = wmma::__float_to_tf32(va.y);
            As[row][kq + 2] = wmma::__float_to_tf32(va.z);
            As[row][kq + 3] = wmma::__float_to_tf32(va.w);
            Bs[row][kq + 0] = wmma::__float_to_tf32(vb.x);
            Bs[row][kq + 1] = wmma::__float_to_tf32(vb.y);
            Bs[row][kq + 2] = wmma::__float_to_tf32(vb.z);
            Bs[row][kq + 3] = wmma::__float_to_tf32(vb.w);
        }
        __syncthreads();

#pragma unroll
        for (int ks = 0; ks < BK / 8; ks++) {
            wmma::fragment<wmma::matrix_a, 16, 16, 8, wmma::precision::tf32,
                           wmma::row_major> af[4];
            wmma::fragment<wmma::matrix_b, 16, 16, 8, wmma::precision::tf32,
                           wmma::col_major> bf[2];
#pragma unroll
            for (int mi = 0; mi < 4; mi++)
                wmma::load_matrix_sync(af[mi], &As[wm * 64 + mi * 16][ks * 8], LDS_PAD);
#pragma unroll
            for (int ni = 0; ni < 2; ni++)
                wmma::load_matrix_sync(bf[ni], &Bs[wn * 32 + ni * 16][ks * 8], LDS_PAD);
#pragma unroll
            for (int mi = 0; mi < 4; mi++)
#pragma unroll
                for (int ni = 0; ni < 2; ni++)
                    wmma::mma_sync(acc[mi][ni], af[mi], bf[ni], acc[mi][ni]);
        }
        __syncthreads();
    }

#pragma unroll
    for (int mi = 0; mi < 4; mi++)
#pragma unroll
        for (int ni = 0; ni < 2; ni++)
            wmma::store_matrix_sync(
                C + (size_t)(bm + wm * 64 + mi * 16) * HID + bn + wn * 32 + ni * 16,
                acc[mi][ni], HID, wmma::mem_row_major);
}

// ---------------------------------------------------------------------------
// RoPE in-place on a [ROWS, NH*HD] tensor.
// ---------------------------------------------------------------------------
__global__ __launch_bounds__(256) void rope_kernel(float* __restrict__ P)
{
    int idx = blockIdx.x * blockDim.x + threadIdx.x;
    if (idx >= ROWS * NH * 32) return;
    int j   = idx & 31;
    int h   = (idx >> 5) & (NH - 1);
    int row = idx >> 9;
    int s   = row & (SS - 1);

    float inv = expf(-(float)j * (9.210340371976184f / 32.0f));
    float ang = (float)s * inv;
    float sn, cs;
    sincosf(ang, &sn, &cs);

    long base = (long)row * HID + h * HD + j;
    float x1 = P[base];
    float x2 = P[base + 32];
    P[base]      = x1 * cs - x2 * sn;
    P[base + 32] = x2 * cs + x1 * sn;
}

// ---------------------------------------------------------------------------
// Flash attention, fp32, causal, 64x64 tiles, online softmax. (known passing)
// ---------------------------------------------------------------------------
__global__ __launch_bounds__(256) void flash_kernel(
    const float* __restrict__ Q, const float* __restrict__ K,
    const float* __restrict__ V, float* __restrict__ AO,
    const int* __restrict__ seq_lens)
{
    const int PAD = 65;
    extern __shared__ float sm[];
    float* Qs = sm;
    float* Ks = Qs + 64 * PAD;
    float* Vs = Ks + 64 * PAD;
    float* Ps = Vs + 64 * PAD;

    const int qt = blockIdx.x, h = blockIdx.y, b = blockIdx.z;
    const int sl = __ldg(&seq_lens[b]);
    const int q0 = qt * 64;
    const int t  = threadIdx.x;
    const int ty = t >> 4;
    const int tx = t & 15;

    const long base = (long)b * SS * HID + (long)h * HD;

    if (q0 >= sl) {
        for (int lin = t; lin < 64 * 16; lin += 256) {
            int r = lin >> 4, c4 = (lin & 15) * 4;
            *(float4*)(AO + base + (long)(q0 + r) * HID + c4) =
                make_float4(0.f, 0.f, 0.f, 0.f);
        }
        return;
    }

    for (int lin = t; lin < 64 * 16; lin += 256) {
        int r = lin >> 4, c4 = (lin & 15) * 4;
        float4 v = *(const float4*)(Q + base + (long)(q0 + r) * HID + c4);
        float* d = &Qs[r * PAD + c4];
        d[0] = v.x; d[1] = v.y; d[2] = v.z; d[3] = v.w;
    }

    float m_i[4], l_i[4], o[4][4];
#pragma unroll
    for (int i = 0; i < 4; i++) {
        m_i[i] = -1e30f; l_i[i] = 0.f;
#pragma unroll
        for (int j = 0; j < 4; j++) o[i][j] = 0.f;
    }
    __syncthreads();

    for (int kt = 0; kt <= qt; kt++) {
        const int k0 = kt * 64;
        for (int lin = t; lin < 64 * 16; lin += 256) {
            int r = lin >> 4, c4 = (lin & 15) * 4;
            long off = base + (long)(k0 + r) * HID + c4;
            float4 kv = *(const float4*)(K + off);
            float4 vv = *(const float4*)(V + off);
            float* dk = &Ks[r * PAD + c4];
            dk[0] = kv.x; dk[1] = kv.y; dk[2] = kv.z; dk[3] = kv.w;
            float* dv = &Vs[r * PAD + c4];
            dv[0] = vv.x; dv[1] = vv.y; dv[2] = vv.z; dv[3] = vv.w;
        }
        __syncthreads();

        float s_acc[4][4];
#pragma unroll
        for (int i = 0; i < 4; i++)
#pragma unroll
            for (int j = 0; j < 4; j++) s_acc[i][j] = 0.f;

#pragma unroll 8
        for (int dd = 0; dd < 64; dd++) {
            float qv[4], kv[4];
#pragma unroll
            for (int i = 0; i < 4; i++) qv[i] = Qs[(ty * 4 + i) * PAD + dd];
#pragma unroll
            for (int j = 0; j < 4; j++) kv[j] = Ks[(tx * 4 + j) * PAD + dd];
#pragma unroll
            for (int i = 0; i < 4; i++)
#pragma unroll
                for (int j = 0; j < 4; j++)
                    s_acc[i][j] = fmaf(qv[i], kv[j], s_acc[i][j]);
        }

        const bool diag = (kt == qt);
#pragma unroll
        for (int i = 0; i < 4; i++) {
            int qg = q0 + ty * 4 + i;
            float mloc = -1e30f;
#pragma unroll
            for (int j = 0; j < 4; j++) {
                float sv = s_acc[i][j] * SCALE;
                if (diag && (k0 + tx * 4 + j) > qg) sv = -1e30f;
                s_acc[i][j] = sv;
                mloc = fmaxf(mloc, sv);
            }
#pragma unroll
            for (int ofs = 8; ofs >= 1; ofs >>= 1)
                mloc = fmaxf(mloc, __shfl_xor_sync(0xffffffffu, mloc, ofs, 16));
            float mnew = fmaxf(m_i[i], mloc);
            float corr = __expf(m_i[i] - mnew);
            m_i[i] = mnew;
            float psum = 0.f;
#pragma unroll
            for (int j = 0; j < 4; j++) {
                float p = __expf(s_acc[i][j] - mnew);
                s_acc[i][j] = p;
                psum += p;
            }
#pragma unroll
            for (int ofs = 8; ofs >= 1; ofs >>= 1)
                psum += __shfl_xor_sync(0xffffffffu, psum, ofs, 16);
            l_i[i] = l_i[i] * corr + psum;
#pragma unroll
            for (int j = 0; j < 4; j++) {
                o[i][j] *= corr;
                Ps[(ty * 4 + i) * PAD + tx * 4 + j] = s_acc[i][j];
            }
        }
        __syncthreads();

#pragma unroll 8
        for (int kk = 0; kk < 64; kk++) {
            float pv[4], vv[4];
#pragma unroll
            for (int i = 0; i < 4; i++) pv[i] = Ps[(ty * 4 + i) * PAD + kk];
#pragma unroll
            for (int j = 0; j < 4; j++) vv[j] = Vs[kk * PAD + tx * 4 + j];
#pragma unroll
            for (int i = 0; i < 4; i++)
#pragma unroll
                for (int j = 0; j < 4; j++)
                    o[i][j] = fmaf(pv[i], vv[j], o[i][j]);
        }
        __syncthreads();
    }

#pragma unroll
    for (int i = 0; i < 4; i++) {
        int r = ty * 4 + i;
        bool valid = (q0 + r) < sl;
        float invl = valid ? (1.f / l_i[i]) : 0.f;
#pragma unroll
        for (int j = 0; j < 4; j++)
            AO[base + (long)(q0 + r) * HID + tx * 4 + j] = o[i][j] * invl;
    }
}

// ---------------------------------------------------------------------------
extern "C" void kernel_launch(void* const* d_in, const int* in_sizes, int n_in,
                              void* d_out, int out_size)
{
    (void)in_sizes; (void)n_in; (void)out_size;
    const float* x  = (const float*)d_in[0];
    const float* Wq = (const float*)d_in[1];
    const float* Wk = (const float*)d_in[2];
    const float* Wv = (const float*)d_in[3];
    const float* Wo = (const float*)d_in[4];
    const int*   sl = (const int*)d_in[5];
    float* out = (float*)d_out;

    float *Q, *K, *V, *AO, *Wt;
    cudaGetSymbolAddress((void**)&Q,  g_Q);
    cudaGetSymbolAddress((void**)&K,  g_K);
    cudaGetSymbolAddress((void**)&V,  g_V);
    cudaGetSymbolAddress((void**)&AO, g_AO);
    cudaGetSymbolAddress((void**)&Wt, g_Wt);

    const int FLASH_SMEM = 4 * 64 * 65 * (int)sizeof(float);  // 66560 B
    cudaFuncSetAttribute(flash_kernel,
                         cudaFuncAttributeMaxDynamicSharedMemorySize, FLASH_SMEM);

    // Transpose all 4 weight matrices into g_Wt (K-contiguous B operand)
    transpose_kernel<<<dim3(32, 32, 4), 256>>>(Wq, Wk, Wv, Wo);

    dim3 gemm_grid(HID / 128, ROWS / 128);   // (8, 64)
    wgemm_kernel<<<gemm_grid, 256>>>(x, Wt + 0 * (size_t)HID * HID, Q);
    wgemm_kernel<<<gemm_grid, 256>>>(x, Wt + 1 * (size_t)HID * HID, K);
    wgemm_kernel<<<gemm_grid, 256>>>(x, Wt + 2 * (size_t)HID * HID, V);

    int rope_n = ROWS * NH * 32;
    rope_kernel<<<rope_n / 256, 256>>>(Q);
    rope_kernel<<<rope_n / 256, 256>>>(K);

    dim3 flash_grid(SS / 64, NH, BB);        // (32, 16, 4)
    flash_kernel<<<flash_grid, 256, FLASH_SMEM>>>(Q, K, V, AO, sl);

    // AO rows past seq_len are exact zeros -> out rows are exact zeros (matches ref)
    wgemm_kernel<<<gemm_grid, 256>>>(AO, Wt + 3 * (size_t)HID * HID, out);
}

// round 5
// speedup vs baseline: 1.4131x; 1.0668x over previous
#include <cuda_runtime.h>
#include <mma.h>
#include <cstdint>
#include <math.h>

using namespace nvcuda;

#define BB   4
#define SS   2048
#define HID  1024
#define NH   16
#define HD   64
#define ROWS (BB*SS)
#define QKVW (3*HID)
#define SCALE 0.125f   // 1/sqrt(64)

// Scratch (alloc-free rule: __device__ globals)
__device__ float g_QKV[ROWS * QKVW];    // fused [rows][Q|K|V]
__device__ float g_AO[ROWS * HID];
__device__ float g_Wt[4 * HID * HID];   // transposed weights: Wt[n][k] = W[k][n]

// ---------------------------------------------------------------------------
// Weight transpose: Wt[z][n][k] = W_z[k][n], 1024x1024 each.
// ---------------------------------------------------------------------------
__global__ __launch_bounds__(256) void transpose_kernel(
    const float* __restrict__ W0, const float* __restrict__ W1,
    const float* __restrict__ W2, const float* __restrict__ W3)
{
    __shared__ float tile[32][33];
    const int z = blockIdx.z;
    const float* W = (z == 0) ? W0 : (z == 1) ? W1 : (z == 2) ? W2 : W3;
    float* T = g_Wt + (size_t)z * HID * HID;
    const int k0 = blockIdx.x * 32, n0 = blockIdx.y * 32;
    const int tx = threadIdx.x & 31, ty = threadIdx.x >> 5;   // 32 x 8
#pragma unroll
    for (int r = 0; r < 4; r++)
        tile[ty + r * 8][tx] = W[(size_t)(k0 + ty + r * 8) * HID + n0 + tx];
    __syncthreads();
#pragma unroll
    for (int r = 0; r < 4; r++)
        T[(size_t)(n0 + ty + r * 8) * HID + k0 + tx] = tile[tx][ty + r * 8];
}

// ---------------------------------------------------------------------------
// WMMA tf32 GEMM with double-buffered smem:
//   C[8192, ncols] = A[8192,1024] @ Bt^T,  Bt is [ncols,1024] K-contiguous.
// Block tile 128x128, BK=16, 256 threads (8 warps), warp tile 64x32.
// Loader: each thread covers rows (t>>2) and (t>>2)+64, cols (t&3)*4..+3
//   -> 2 float4 per matrix per stage = full 128x16 tile.
// ---------------------------------------------------------------------------
#define BK2  16
#define PAD2 20   // 16 + 4 floats

__global__ __launch_bounds__(256) void wgemm_kernel(
    const float* __restrict__ A, const float* __restrict__ Bt,
    float* __restrict__ C, int ldc)
{
    __shared__ float As[2][128][PAD2];
    __shared__ float Bs[2][128][PAD2];

    const int t   = threadIdx.x;
    const int wid = t >> 5;
    const int bm  = blockIdx.y * 128;
    const int bn  = blockIdx.x * 128;
    const int wm  = wid & 1;     // 0..1 -> 64-row strip
    const int wn  = wid >> 1;    // 0..3 -> 32-col strip
    const int row = t >> 2;      // 0..63 (loader row; also row+64)
    const int kq  = (t & 3) * 4; // 0,4,8,12

    const float* Ap0 = A  + (size_t)(bm + row) * HID + kq;
    const float* Ap1 = A  + (size_t)(bm + row + 64) * HID + kq;
    const float* Bp0 = Bt + (size_t)(bn + row) * HID + kq;
    const float* Bp1 = Bt + (size_t)(bn + row + 64) * HID + kq;

    wmma::fragment<wmma::accumulator, 16, 16, 8, float> acc[4][2];
#pragma unroll
    for (int mi = 0; mi < 4; mi++)
#pragma unroll
        for (int ni = 0; ni < 2; ni++)
            wmma::fill_fragment(acc[mi][ni], 0.0f);

#define ST_TILE(buf, r, v)                                    \
    do {                                                      \
        (buf)[r][kq + 0] = wmma::__float_to_tf32((v).x);      \
        (buf)[r][kq + 1] = wmma::__float_to_tf32((v).y);      \
        (buf)[r][kq + 2] = wmma::__float_to_tf32((v).z);      \
        (buf)[r][kq + 3] = wmma::__float_to_tf32((v).w);      \
    } while (0)

    // Preload tile 0
    {
        float4 a0 = *(const float4*)Ap0;
        float4 a1 = *(const float4*)Ap1;
        float4 b0 = *(const float4*)Bp0;
        float4 b1 = *(const float4*)Bp1;
        ST_TILE(As[0], row, a0);
        ST_TILE(As[0], row + 64, a1);
        ST_TILE(Bs[0], row, b0);
        ST_TILE(Bs[0], row + 64, b1);
    }
    __syncthreads();

    const int NT = HID / BK2;   // 64
    for (int k = 0; k < NT; k++) {
        const int cur = k & 1, nxt = cur ^ 1;
        float4 a0, a1, b0, b1;
        const bool more = (k + 1) < NT;
        if (more) {
            const int ko = (k + 1) * BK2;
            a0 = *(const float4*)(Ap0 + ko);
            a1 = *(const float4*)(Ap1 + ko);
            b0 = *(const float4*)(Bp0 + ko);
            b1 = *(const float4*)(Bp1 + ko);
        }

        // MMA on current buffer (2 K=8 sub-steps)
#pragma unroll
        for (int ks = 0; ks < BK2 / 8; ks++) {
            wmma::fragment<wmma::matrix_a, 16, 16, 8, wmma::precision::tf32,
                           wmma::row_major> af[4];
            wmma::fragment<wmma::matrix_b, 16, 16, 8, wmma::precision::tf32,
                           wmma::col_major> bf[2];
#pragma unroll
            for (int mi = 0; mi < 4; mi++)
                wmma::load_matrix_sync(af[mi], &As[cur][wm * 64 + mi * 16][ks * 8], PAD2);
#pragma unroll
            for (int ni = 0; ni < 2; ni++)
                wmma::load_matrix_sync(bf[ni], &Bs[cur][wn * 32 + ni * 16][ks * 8], PAD2);
#pragma unroll
            for (int mi = 0; mi < 4; mi++)
#pragma unroll
                for (int ni = 0; ni < 2; ni++)
                    wmma::mma_sync(acc[mi][ni], af[mi], bf[ni], acc[mi][ni]);
        }

        if (more) {
            ST_TILE(As[nxt], row, a0);
            ST_TILE(As[nxt], row + 64, a1);
            ST_TILE(Bs[nxt], row, b0);
            ST_TILE(Bs[nxt], row + 64, b1);
        }
        __syncthreads();
    }
#undef ST_TILE

#pragma unroll
    for (int mi = 0; mi < 4; mi++)
#pragma unroll
        for (int ni = 0; ni < 2; ni++)
            wmma::store_matrix_sync(
                C + (size_t)(bm + wm * 64 + mi * 16) * ldc + bn + wn * 32 + ni * 16,
                acc[mi][ni], ldc, wmma::mem_row_major);
}

// ---------------------------------------------------------------------------
// RoPE in-place on the fused QKV tensor: rotates both Q (cols 0..1023) and
// K (cols 1024..2047). h spans 0..31 (16 Q-heads then 16 K-heads).
// ---------------------------------------------------------------------------
__global__ __launch_bounds__(256) void rope_kernel(float* __restrict__ P)
{
    int idx = blockIdx.x * blockDim.x + threadIdx.x;
    int j   = idx & 31;
    int h   = (idx >> 5) & 31;
    int row = idx >> 10;
    int s   = row & (SS - 1);

    float inv = expf(-(float)j * (9.210340371976184f / 32.0f));
    float ang = (float)s * inv;
    float sn, cs;
    sincosf(ang, &sn, &cs);

    long base = (long)row * QKVW + h * HD + j;
    float x1 = P[base];
    float x2 = P[base + 32];
    P[base]      = x1 * cs - x2 * sn;
    P[base + 32] = x2 * cs + x1 * sn;
}

// ---------------------------------------------------------------------------
// Flash attention, fp32, causal, 64x64 tiles, online softmax.
// Reads fused QKV (row stride 3072), writes AO (row stride 1024).
// ---------------------------------------------------------------------------
__global__ __launch_bounds__(256) void flash_kernel(
    const float* __restrict__ QKV, float* __restrict__ AO,
    const int* __restrict__ seq_lens)
{
    const int PAD = 65;
    extern __shared__ float sm[];
    float* Qs = sm;
    float* Ks = Qs + 64 * PAD;
    float* Vs = Ks + 64 * PAD;
    float* Ps = Vs + 64 * PAD;

    const int qt = blockIdx.x, h = blockIdx.y, b = blockIdx.z;
    const int sl = __ldg(&seq_lens[b]);
    const int q0 = qt * 64;
    const int t  = threadIdx.x;
    const int ty = t >> 4;
    const int tx = t & 15;

    const long qkv_base = (long)b * SS * QKVW + (long)h * HD;
    const long ao_base  = (long)b * SS * HID  + (long)h * HD;

    if (q0 >= sl) {
        for (int lin = t; lin < 64 * 16; lin += 256) {
            int r = lin >> 4, c4 = (lin & 15) * 4;
            *(float4*)(AO + ao_base + (long)(q0 + r) * HID + c4) =
                make_float4(0.f, 0.f, 0.f, 0.f);
        }
        return;
    }

    for (int lin = t; lin < 64 * 16; lin += 256) {
        int r = lin >> 4, c4 = (lin & 15) * 4;
        float4 v = *(const float4*)(QKV + qkv_base + (long)(q0 + r) * QKVW + c4);
        float* d = &Qs[r * PAD + c4];
        d[0] = v.x; d[1] = v.y; d[2] = v.z; d[3] = v.w;
    }

    float m_i[4], l_i[4], o[4][4];
#pragma unroll
    for (int i = 0; i < 4; i++) {
        m_i[i] = -1e30f; l_i[i] = 0.f;
#pragma unroll
        for (int j = 0; j < 4; j++) o[i][j] = 0.f;
    }
    __syncthreads();

    for (int kt = 0; kt <= qt; kt++) {
        const int k0 = kt * 64;
        for (int lin = t; lin < 64 * 16; lin += 256) {
            int r = lin >> 4, c4 = (lin & 15) * 4;
            long off = qkv_base + (long)(k0 + r) * QKVW + c4;
            float4 kv = *(const float4*)(QKV + off + HID);
            float4 vv = *(const float4*)(QKV + off + 2 * HID);
            float* dk = &Ks[r * PAD + c4];
            dk[0] = kv.x; dk[1] = kv.y; dk[2] = kv.z; dk[3] = kv.w;
            float* dv = &Vs[r * PAD + c4];
            dv[0] = vv.x; dv[1] = vv.y; dv[2] = vv.z; dv[3] = vv.w;
        }
        __syncthreads();

        float s_acc[4][4];
#pragma unroll
        for (int i = 0; i < 4; i++)
#pragma unroll
            for (int j = 0; j < 4; j++) s_acc[i][j] = 0.f;

#pragma unroll 8
        for (int dd = 0; dd < 64; dd++) {
            float qv[4], kv[4];
#pragma unroll
            for (int i = 0; i < 4; i++) qv[i] = Qs[(ty * 4 + i) * PAD + dd];
#pragma unroll
            for (int j = 0; j < 4; j++) kv[j] = Ks[(tx * 4 + j) * PAD + dd];
#pragma unroll
            for (int i = 0; i < 4; i++)
#pragma unroll
                for (int j = 0; j < 4; j++)
                    s_acc[i][j] = fmaf(qv[i], kv[j], s_acc[i][j]);
        }

        const bool diag = (kt == qt);
#pragma unroll
        for (int i = 0; i < 4; i++) {
            int qg = q0 + ty * 4 + i;
            float mloc = -1e30f;
#pragma unroll
            for (int j = 0; j < 4; j++) {
                float sv = s_acc[i][j] * SCALE;
                if (diag && (k0 + tx * 4 + j) > qg) sv = -1e30f;
                s_acc[i][j] = sv;
                mloc = fmaxf(mloc, sv);
            }
#pragma unroll
            for (int ofs = 8; ofs >= 1; ofs >>= 1)
                mloc = fmaxf(mloc, __shfl_xor_sync(0xffffffffu, mloc, ofs, 16));
            float mnew = fmaxf(m_i[i], mloc);
            float corr = __expf(m_i[i] - mnew);
            m_i[i] = mnew;
            float psum = 0.f;
#pragma unroll
            for (int j = 0; j < 4; j++) {
                float p = __expf(s_acc[i][j] - mnew);
                s_acc[i][j] = p;
                psum += p;
            }
#pragma unroll
            for (int ofs = 8; ofs >= 1; ofs >>= 1)
                psum += __shfl_xor_sync(0xffffffffu, psum, ofs, 16);
            l_i[i] = l_i[i] * corr + psum;
#pragma unroll
            for (int j = 0; j < 4; j++) {
                o[i][j] *= corr;
                Ps[(ty * 4 + i) * PAD + tx * 4 + j] = s_acc[i][j];
            }
        }
        __syncthreads();

#pragma unroll 8
        for (int kk = 0; kk < 64; kk++) {
            float pv[4], vv[4];
#pragma unroll
            for (int i = 0; i < 4; i++) pv[i] = Ps[(ty * 4 + i) * PAD + kk];
#pragma unroll
            for (int j = 0; j < 4; j++) vv[j] = Vs[kk * PAD + tx * 4 + j];
#pragma unroll
            for (int i = 0; i < 4; i++)
#pragma unroll
                for (int j = 0; j < 4; j++)
                    o[i][j] = fmaf(pv[i], vv[j], o[i][j]);
        }
        __syncthreads();
    }

#pragma unroll
    for (int i = 0; i < 4; i++) {
        int r = ty * 4 + i;
        bool valid = (q0 + r) < sl;
        float invl = valid ? (1.f / l_i[i]) : 0.f;
#pragma unroll
        for (int j = 0; j < 4; j++)
            AO[ao_base + (long)(q0 + r) * HID + tx * 4 + j] = o[i][j] * invl;
    }
}

// ---------------------------------------------------------------------------
extern "C" void kernel_launch(void* const* d_in, const int* in_sizes, int n_in,
                              void* d_out, int out_size)
{
    (void)in_sizes; (void)n_in; (void)out_size;
    const float* x  = (const float*)d_in[0];
    const float* Wq = (const float*)d_in[1];
    const float* Wk = (const float*)d_in[2];
    const float* Wv = (const float*)d_in[3];
    const float* Wo = (const float*)d_in[4];
    const int*   sl = (const int*)d_in[5];
    float* out = (float*)d_out;

    float *QKV, *AO, *Wt;
    cudaGetSymbolAddress((void**)&QKV, g_QKV);
    cudaGetSymbolAddress((void**)&AO,  g_AO);
    cudaGetSymbolAddress((void**)&Wt,  g_Wt);

    const int FLASH_SMEM = 4 * 64 * 65 * (int)sizeof(float);  // 66560 B
    cudaFuncSetAttribute(flash_kernel,
                         cudaFuncAttributeMaxDynamicSharedMemorySize, FLASH_SMEM);

    // Transpose all 4 weight matrices into g_Wt (K-contiguous B operand).
    // Slots 0..2 = [Wq|Wk|Wv]^T form a contiguous [3072][1024] fused weight.
    transpose_kernel<<<dim3(32, 32, 4), 256>>>(Wq, Wk, Wv, Wo);

    // Fused QKV GEMM: [8192,1024] @ [3072,1024]^T -> [8192,3072]
    wgemm_kernel<<<dim3(QKVW / 128, ROWS / 128), 256>>>(x, Wt, QKV, QKVW);

    // Fused RoPE over Q and K halves (cols 0..2047)
    rope_kernel<<<(ROWS * 1024) / 256, 256>>>(QKV);

    dim3 flash_grid(SS / 64, NH, BB);        // (32, 16, 4)
    flash_kernel<<<flash_grid, 256, FLASH_SMEM>>>(QKV, AO, sl);

    // Output projection: AO rows past seq_len are exact zeros -> out rows zero.
    wgemm_kernel<<<dim3(HID / 128, ROWS / 128), 256>>>(
        AO, Wt + 3 * (size_t)HID * HID, out, HID);
}

// round 6
// speedup vs baseline: 1.8822x; 1.3320x over previous
#include <cuda_runtime.h>
#include <mma.h>
#include <cstdint>
#include <math.h>

using namespace nvcuda;

#define BB   4
#define SS   2048
#define HID  1024
#define NH   16
#define HD   64
#define ROWS (BB*SS)
#define QKVW (3*HID)
#define SCALE 0.125f   // 1/sqrt(64)

// Scratch (alloc-free rule: __device__ globals)
__device__ float g_QKV[ROWS * QKVW];    // fused [rows][Q|K|V]
__device__ float g_AO[ROWS * HID];
__device__ float g_Wt[4 * HID * HID];   // transposed weights: Wt[n][k] = W[k][n]

// ---------------------------------------------------------------------------
// Weight transpose: Wt[z][n][k] = W_z[k][n], 1024x1024 each.
// ---------------------------------------------------------------------------
__global__ __launch_bounds__(256) void transpose_kernel(
    const float* __restrict__ W0, const float* __restrict__ W1,
    const float* __restrict__ W2, const float* __restrict__ W3)
{
    __shared__ float tile[32][33];
    const int z = blockIdx.z;
    const float* W = (z == 0) ? W0 : (z == 1) ? W1 : (z == 2) ? W2 : W3;
    float* T = g_Wt + (size_t)z * HID * HID;
    const int k0 = blockIdx.x * 32, n0 = blockIdx.y * 32;
    const int tx = threadIdx.x & 31, ty = threadIdx.x >> 5;   // 32 x 8
#pragma unroll
    for (int r = 0; r < 4; r++)
        tile[ty + r * 8][tx] = W[(size_t)(k0 + ty + r * 8) * HID + n0 + tx];
    __syncthreads();
#pragma unroll
    for (int r = 0; r < 4; r++)
        T[(size_t)(n0 + ty + r * 8) * HID + k0 + tx] = tile[tx][ty + r * 8];
}

// ---------------------------------------------------------------------------
// WMMA tf32 GEMM with double-buffered smem (unchanged from round 5, passing).
// ---------------------------------------------------------------------------
#define BK2  16
#define PAD2 20   // 16 + 4 floats

__global__ __launch_bounds__(256) void wgemm_kernel(
    const float* __restrict__ A, const float* __restrict__ Bt,
    float* __restrict__ C, int ldc)
{
    __shared__ float As[2][128][PAD2];
    __shared__ float Bs[2][128][PAD2];

    const int t   = threadIdx.x;
    const int wid = t >> 5;
    const int bm  = blockIdx.y * 128;
    const int bn  = blockIdx.x * 128;
    const int wm  = wid & 1;
    const int wn  = wid >> 1;
    const int row = t >> 2;      // 0..63 (also row+64)
    const int kq  = (t & 3) * 4;

    const float* Ap0 = A  + (size_t)(bm + row) * HID + kq;
    const float* Ap1 = A  + (size_t)(bm + row + 64) * HID + kq;
    const float* Bp0 = Bt + (size_t)(bn + row) * HID + kq;
    const float* Bp1 = Bt + (size_t)(bn + row + 64) * HID + kq;

    wmma::fragment<wmma::accumulator, 16, 16, 8, float> acc[4][2];
#pragma unroll
    for (int mi = 0; mi < 4; mi++)
#pragma unroll
        for (int ni = 0; ni < 2; ni++)
            wmma::fill_fragment(acc[mi][ni], 0.0f);

#define ST_TILE(buf, r, v)                                    \
    do {                                                      \
        (buf)[r][kq + 0] = wmma::__float_to_tf32((v).x);      \
        (buf)[r][kq + 1] = wmma::__float_to_tf32((v).y);      \
        (buf)[r][kq + 2] = wmma::__float_to_tf32((v).z);      \
        (buf)[r][kq + 3] = wmma::__float_to_tf32((v).w);      \
    } while (0)

    {
        float4 a0 = *(const float4*)Ap0;
        float4 a1 = *(const float4*)Ap1;
        float4 b0 = *(const float4*)Bp0;
        float4 b1 = *(const float4*)Bp1;
        ST_TILE(As[0], row, a0);
        ST_TILE(As[0], row + 64, a1);
        ST_TILE(Bs[0], row, b0);
        ST_TILE(Bs[0], row + 64, b1);
    }
    __syncthreads();

    const int NT = HID / BK2;   // 64
    for (int k = 0; k < NT; k++) {
        const int cur = k & 1, nxt = cur ^ 1;
        float4 a0, a1, b0, b1;
        const bool more = (k + 1) < NT;
        if (more) {
            const int ko = (k + 1) * BK2;
            a0 = *(const float4*)(Ap0 + ko);
            a1 = *(const float4*)(Ap1 + ko);
            b0 = *(const float4*)(Bp0 + ko);
            b1 = *(const float4*)(Bp1 + ko);
        }

#pragma unroll
        for (int ks = 0; ks < BK2 / 8; ks++) {
            wmma::fragment<wmma::matrix_a, 16, 16, 8, wmma::precision::tf32,
                           wmma::row_major> af[4];
            wmma::fragment<wmma::matrix_b, 16, 16, 8, wmma::precision::tf32,
                           wmma::col_major> bf[2];
#pragma unroll
            for (int mi = 0; mi < 4; mi++)
                wmma::load_matrix_sync(af[mi], &As[cur][wm * 64 + mi * 16][ks * 8], PAD2);
#pragma unroll
            for (int ni = 0; ni < 2; ni++)
                wmma::load_matrix_sync(bf[ni], &Bs[cur][wn * 32 + ni * 16][ks * 8], PAD2);
#pragma unroll
            for (int mi = 0; mi < 4; mi++)
#pragma unroll
                for (int ni = 0; ni < 2; ni++)
                    wmma::mma_sync(acc[mi][ni], af[mi], bf[ni], acc[mi][ni]);
        }

        if (more) {
            ST_TILE(As[nxt], row, a0);
            ST_TILE(As[nxt], row + 64, a1);
            ST_TILE(Bs[nxt], row, b0);
            ST_TILE(Bs[nxt], row + 64, b1);
        }
        __syncthreads();
    }
#undef ST_TILE

#pragma unroll
    for (int mi = 0; mi < 4; mi++)
#pragma unroll
        for (int ni = 0; ni < 2; ni++)
            wmma::store_matrix_sync(
                C + (size_t)(bm + wm * 64 + mi * 16) * ldc + bn + wn * 32 + ni * 16,
                acc[mi][ni], ldc, wmma::mem_row_major);
}

// ---------------------------------------------------------------------------
// RoPE in-place on the fused QKV tensor (Q and K halves).
// ---------------------------------------------------------------------------
__global__ __launch_bounds__(256) void rope_kernel(float* __restrict__ P)
{
    int idx = blockIdx.x * blockDim.x + threadIdx.x;
    int j   = idx & 31;
    int h   = (idx >> 5) & 31;
    int row = idx >> 10;
    int s   = row & (SS - 1);

    float inv = expf(-(float)j * (9.210340371976184f / 32.0f));
    float ang = (float)s * inv;
    float sn, cs;
    sincosf(ang, &sn, &cs);

    long base = (long)row * QKVW + h * HD + j;
    float x1 = P[base];
    float x2 = P[base + 32];
    P[base]      = x1 * cs - x2 * sn;
    P[base + 32] = x2 * cs + x1 * sn;
}

// ---------------------------------------------------------------------------
// Flash attention on mma.sync tf32 (m16n8k8).
// BQ=128 q-rows per CTA, kv tiles of 64, 8 warps; each warp owns 16 q-rows.
// Fragment layouts (PTX m16n8k8 tf32; gid=lane>>2, q4=lane&3):
//   A: a0(g,q4) a1(g+8,q4) a2(g,q4+4) a3(g+8,q4+4)
//   B: b0(k=q4,n=gid) b1(k=q4+4,n=gid)
//   C: c0(g,2q4) c1(g,2q4+1) c2(g+8,2q4) c3(g+8,2q4+1)
// ---------------------------------------------------------------------------
#define FPAD 68   // 68 % 32 == 4 -> fragment gathers are bank-conflict-free

__device__ __forceinline__ float tf32f(float x) {
    uint32_t u;
    asm("cvt.rna.tf32.f32 %0, %1;" : "=r"(u) : "f"(x));
    return __uint_as_float(u);
}
__device__ __forceinline__ void mma_tf32(float* d, const uint32_t* a,
                                         const uint32_t* b) {
    asm volatile(
        "mma.sync.aligned.m16n8k8.row.col.f32.tf32.tf32.f32 "
        "{%0,%1,%2,%3}, {%4,%5,%6,%7}, {%8,%9}, {%0,%1,%2,%3};\n"
        : "+f"(d[0]), "+f"(d[1]), "+f"(d[2]), "+f"(d[3])
        : "r"(a[0]), "r"(a[1]), "r"(a[2]), "r"(a[3]), "r"(b[0]), "r"(b[1]));
}

__global__ __launch_bounds__(256, 2) void flashmma_kernel(
    const float* __restrict__ QKV, float* __restrict__ AO,
    const int* __restrict__ seq_lens)
{
    extern __shared__ float sm[];
    float* Ps = sm;                  // [128][FPAD]  (Q staging, then P)
    float* Ks = Ps + 128 * FPAD;     // [64][FPAD]
    float* Vs = Ks + 64 * FPAD;      // [64][FPAD]

    const int bx = blockIdx.x, h = blockIdx.y, b = blockIdx.z;
    const int sl = __ldg(&seq_lens[b]);
    const int q0 = bx * 128;
    const int t  = threadIdx.x;
    const int wid = t >> 5, lane = t & 31;
    const int gid = lane >> 2, q4 = lane & 3;
    const int wr  = wid * 16;

    const long qkv_base = (long)b * SS * QKVW + (long)h * HD;
    const long ao_base  = (long)b * SS * HID  + (long)h * HD;

    if (q0 >= sl) {
        for (int lin = t; lin < 128 * 16; lin += 256) {
            int r = lin >> 4, c4 = (lin & 15) * 4;
            *(float4*)(AO + ao_base + (long)(q0 + r) * HID + c4) =
                make_float4(0.f, 0.f, 0.f, 0.f);
        }
        return;
    }

    // Stage Q (pre-scaled, tf32) into Ps, then extract per-warp A-fragments.
    for (int lin = t; lin < 128 * 16; lin += 256) {
        int r = lin >> 4, c4 = (lin & 15) * 4;
        float4 v = *(const float4*)(QKV + qkv_base + (long)(q0 + r) * QKVW + c4);
        float* d = &Ps[r * FPAD + c4];
        d[0] = tf32f(v.x * SCALE); d[1] = tf32f(v.y * SCALE);
        d[2] = tf32f(v.z * SCALE); d[3] = tf32f(v.w * SCALE);
    }
    __syncthreads();

    uint32_t qa[8][4];
#pragma unroll
    for (int kf = 0; kf < 8; kf++) {
        const float* p0 = &Ps[(wr + gid) * FPAD + kf * 8 + q4];
        const float* p1 = &Ps[(wr + gid + 8) * FPAD + kf * 8 + q4];
        qa[kf][0] = __float_as_uint(p0[0]);
        qa[kf][1] = __float_as_uint(p1[0]);
        qa[kf][2] = __float_as_uint(p0[4]);
        qa[kf][3] = __float_as_uint(p1[4]);
    }
    // Each warp later overwrites only its own Ps rows -> no cross-warp hazard.

    float ofr[8][4];
#pragma unroll
    for (int nf = 0; nf < 8; nf++)
#pragma unroll
        for (int e = 0; e < 4; e++) ofr[nf][e] = 0.f;
    float m0 = -1e30f, m1 = -1e30f, l0 = 0.f, l1 = 0.f;

    const int r0g = q0 + wr + gid;
    const int r1g = r0g + 8;

    const int n_kt = min(2 * bx + 2, (sl + 63) >> 6);
    for (int kt = 0; kt < n_kt; kt++) {
        const int k0 = kt * 64;
        __syncthreads();   // Ks/Vs free to overwrite (readers done)
        for (int lin = t; lin < 64 * 16; lin += 256) {
            int r = lin >> 4, c4 = (lin & 15) * 4;
            long off = qkv_base + (long)(k0 + r) * QKVW + c4;
            float4 kv = *(const float4*)(QKV + off + HID);
            float4 vv = *(const float4*)(QKV + off + 2 * HID);
            float* dk = &Ks[r * FPAD + c4];
            dk[0] = tf32f(kv.x); dk[1] = tf32f(kv.y);
            dk[2] = tf32f(kv.z); dk[3] = tf32f(kv.w);
            float* dv = &Vs[r * FPAD + c4];
            dv[0] = tf32f(vv.x); dv[1] = tf32f(vv.y);
            dv[2] = tf32f(vv.z); dv[3] = tf32f(vv.w);
        }
        __syncthreads();

        // S = Q @ K^T  (scaled already via Q)
        float sfr[8][4];
#pragma unroll
        for (int nf = 0; nf < 8; nf++)
#pragma unroll
            for (int e = 0; e < 4; e++) sfr[nf][e] = 0.f;

#pragma unroll
        for (int kf = 0; kf < 8; kf++) {
#pragma unroll
            for (int nf = 0; nf < 8; nf++) {
                uint32_t bb[2];
                const float* kp = &Ks[(nf * 8 + gid) * FPAD + kf * 8 + q4];
                bb[0] = __float_as_uint(kp[0]);
                bb[1] = __float_as_uint(kp[4]);
                mma_tf32(sfr[nf], qa[kf], bb);
            }
        }

        // Causal mask (only diagonal-region tiles need it)
        if (k0 + 63 > q0 + wr) {
#pragma unroll
            for (int nf = 0; nf < 8; nf++) {
                int c0 = k0 + nf * 8 + 2 * q4, c1 = c0 + 1;
                if (c0 > r0g) sfr[nf][0] = -1e30f;
                if (c1 > r0g) sfr[nf][1] = -1e30f;
                if (c0 > r1g) sfr[nf][2] = -1e30f;
                if (c1 > r1g) sfr[nf][3] = -1e30f;
            }
        }

        // Online softmax (rows are quad-local: reduce over lane^1, lane^2)
        float tm0 = -1e30f, tm1 = -1e30f;
#pragma unroll
        for (int nf = 0; nf < 8; nf++) {
            tm0 = fmaxf(tm0, fmaxf(sfr[nf][0], sfr[nf][1]));
            tm1 = fmaxf(tm1, fmaxf(sfr[nf][2], sfr[nf][3]));
        }
        tm0 = fmaxf(tm0, __shfl_xor_sync(0xffffffffu, tm0, 1));
        tm0 = fmaxf(tm0, __shfl_xor_sync(0xffffffffu, tm0, 2));
        tm1 = fmaxf(tm1, __shfl_xor_sync(0xffffffffu, tm1, 1));
        tm1 = fmaxf(tm1, __shfl_xor_sync(0xffffffffu, tm1, 2));

        float mn0 = fmaxf(m0, tm0), mn1 = fmaxf(m1, tm1);
        float corr0 = __expf(m0 - mn0), corr1 = __expf(m1 - mn1);
        m0 = mn0; m1 = mn1;

        float s0 = 0.f, s1 = 0.f;
#pragma unroll
        for (int nf = 0; nf < 8; nf++) {
            float p0 = __expf(sfr[nf][0] - mn0);
            float p1 = __expf(sfr[nf][1] - mn0);
            float p2 = __expf(sfr[nf][2] - mn1);
            float p3 = __expf(sfr[nf][3] - mn1);
            s0 += p0 + p1; s1 += p2 + p3;
            *(float2*)&Ps[(wr + gid) * FPAD + nf * 8 + 2 * q4] =
                make_float2(tf32f(p0), tf32f(p1));
            *(float2*)&Ps[(wr + gid + 8) * FPAD + nf * 8 + 2 * q4] =
                make_float2(tf32f(p2), tf32f(p3));
        }
        s0 += __shfl_xor_sync(0xffffffffu, s0, 1);
        s0 += __shfl_xor_sync(0xffffffffu, s0, 2);
        s1 += __shfl_xor_sync(0xffffffffu, s1, 1);
        s1 += __shfl_xor_sync(0xffffffffu, s1, 2);
        l0 = l0 * corr0 + s0;
        l1 = l1 * corr1 + s1;

#pragma unroll
        for (int nf = 0; nf < 8; nf++) {
            ofr[nf][0] *= corr0; ofr[nf][1] *= corr0;
            ofr[nf][2] *= corr1; ofr[nf][3] *= corr1;
        }
        __syncwarp();   // P visible within warp

        // O += P @ V
#pragma unroll
        for (int kf = 0; kf < 8; kf++) {
            uint32_t pa[4];
            const float* pp0 = &Ps[(wr + gid) * FPAD + kf * 8 + q4];
            const float* pp1 = &Ps[(wr + gid + 8) * FPAD + kf * 8 + q4];
            pa[0] = __float_as_uint(pp0[0]);
            pa[1] = __float_as_uint(pp1[0]);
            pa[2] = __float_as_uint(pp0[4]);
            pa[3] = __float_as_uint(pp1[4]);
#pragma unroll
            for (int nf = 0; nf < 8; nf++) {
                uint32_t bb[2];
                const float* vp0 = &Vs[(kf * 8 + q4) * FPAD + nf * 8 + gid];
                const float* vp1 = &Vs[(kf * 8 + q4 + 4) * FPAD + nf * 8 + gid];
                bb[0] = __float_as_uint(vp0[0]);
                bb[1] = __float_as_uint(vp1[0]);
                mma_tf32(ofr[nf], pa, bb);
            }
        }
    }

    // Epilogue: normalize and store, zeroing rows past seq_len.
    const float inv0 = (r0g < sl) ? (1.f / l0) : 0.f;
    const float inv1 = (r1g < sl) ? (1.f / l1) : 0.f;
#pragma unroll
    for (int nf = 0; nf < 8; nf++) {
        *(float2*)(AO + ao_base + (long)r0g * HID + nf * 8 + 2 * q4) =
            make_float2(ofr[nf][0] * inv0, ofr[nf][1] * inv0);
        *(float2*)(AO + ao_base + (long)r1g * HID + nf * 8 + 2 * q4) =
            make_float2(ofr[nf][2] * inv1, ofr[nf][3] * inv1);
    }
}

// ---------------------------------------------------------------------------
extern "C" void kernel_launch(void* const* d_in, const int* in_sizes, int n_in,
                              void* d_out, int out_size)
{
    (void)in_sizes; (void)n_in; (void)out_size;
    const float* x  = (const float*)d_in[0];
    const float* Wq = (const float*)d_in[1];
    const float* Wk = (const float*)d_in[2];
    const float* Wv = (const float*)d_in[3];
    const float* Wo = (const float*)d_in[4];
    const int*   sl = (const int*)d_in[5];
    float* out = (float*)d_out;

    float *QKV, *AO, *Wt;
    cudaGetSymbolAddress((void**)&QKV, g_QKV);
    cudaGetSymbolAddress((void**)&AO,  g_AO);
    cudaGetSymbolAddress((void**)&Wt,  g_Wt);

    const int FLASH_SMEM = (128 + 64 + 64) * FPAD * (int)sizeof(float);  // 69632
    cudaFuncSetAttribute(flashmma_kernel,
                         cudaFuncAttributeMaxDynamicSharedMemorySize, FLASH_SMEM);

    transpose_kernel<<<dim3(32, 32, 4), 256>>>(Wq, Wk, Wv, Wo);

    // Fused QKV GEMM: [8192,1024] @ [3072,1024]^T -> [8192,3072]
    wgemm_kernel<<<dim3(QKVW / 128, ROWS / 128), 256>>>(x, Wt, QKV, QKVW);

    // Fused RoPE over Q and K halves
    rope_kernel<<<(ROWS * 1024) / 256, 256>>>(QKV);

    dim3 flash_grid(SS / 128, NH, BB);       // (16, 16, 4)
    flashmma_kernel<<<flash_grid, 256, FLASH_SMEM>>>(QKV, AO, sl);

    // Output projection: AO rows past seq_len are exact zeros -> out rows zero.
    wgemm_kernel<<<dim3(HID / 128, ROWS / 128), 256>>>(
        AO, Wt + 3 * (size_t)HID * HID, out, HID);
}

// round 7
// speedup vs baseline: 2.6312x; 1.3979x over previous
#include <cuda_runtime.h>
#include <cstdint>
#include <math.h>

#define BB   4
#define SS   2048
#define HID  1024
#define NH   16
#define HD   64
#define ROWS (BB*SS)
#define QKVW (3*HID)
#define SCALE 0.125f   // 1/sqrt(64)

// Scratch (alloc-free rule: __device__ globals)
__device__ float g_QKV[ROWS * QKVW];    // fused [rows][Q|K|V]
__device__ float g_AO[ROWS * HID];
__device__ float g_Wt[4 * HID * HID];   // transposed weights: Wt[n][k] = W[k][n]

__device__ __forceinline__ float tf32f(float x) {
    uint32_t u;
    asm("cvt.rna.tf32.f32 %0, %1;" : "=r"(u) : "f"(x));
    return __uint_as_float(u);
}
__device__ __forceinline__ void mma_tf32(float* d, const uint32_t* a,
                                         const uint32_t* b) {
    asm volatile(
        "mma.sync.aligned.m16n8k8.row.col.f32.tf32.tf32.f32 "
        "{%0,%1,%2,%3}, {%4,%5,%6,%7}, {%8,%9}, {%0,%1,%2,%3};\n"
        : "+f"(d[0]), "+f"(d[1]), "+f"(d[2]), "+f"(d[3])
        : "r"(a[0]), "r"(a[1]), "r"(a[2]), "r"(a[3]), "r"(b[0]), "r"(b[1]));
}

// ---------------------------------------------------------------------------
// Weight transpose: Wt[z][n][k] = W_z[k][n], 1024x1024 each.
// ---------------------------------------------------------------------------
__global__ __launch_bounds__(256) void transpose_kernel(
    const float* __restrict__ W0, const float* __restrict__ W1,
    const float* __restrict__ W2, const float* __restrict__ W3)
{
    __shared__ float tile[32][33];
    const int z = blockIdx.z;
    const float* W = (z == 0) ? W0 : (z == 1) ? W1 : (z == 2) ? W2 : W3;
    float* T = g_Wt + (size_t)z * HID * HID;
    const int k0 = blockIdx.x * 32, n0 = blockIdx.y * 32;
    const int tx = threadIdx.x & 31, ty = threadIdx.x >> 5;   // 32 x 8
#pragma unroll
    for (int r = 0; r < 4; r++)
        tile[ty + r * 8][tx] = W[(size_t)(k0 + ty + r * 8) * HID + n0 + tx];
    __syncthreads();
#pragma unroll
    for (int r = 0; r < 4; r++)
        T[(size_t)(n0 + ty + r * 8) * HID + k0 + tx] = tile[tx][ty + r * 8];
}

// ---------------------------------------------------------------------------
// Raw mma.sync tf32 GEMM: C[8192, ncols] = A[8192,1024] @ Bt^T.
// Block 128x128, BK=16 double-buffered, 8 warps as 2(M)x4(N).
// Warp tile 64x32 = 4x4 m16n8 accumulators.
// Fragment gathers: row stride GPAD=20 -> (20*gid + q4) mod 32 covers all 32
// banks (conflict-free).
// ---------------------------------------------------------------------------
#define GPAD 20

__global__ __launch_bounds__(256, 2) void rgemm_kernel(
    const float* __restrict__ A, const float* __restrict__ Bt,
    float* __restrict__ C, int ldc)
{
    __shared__ float As[2][128][GPAD];
    __shared__ float Bs[2][128][GPAD];

    const int t    = threadIdx.x;
    const int wid  = t >> 5, lane = t & 31;
    const int gid  = lane >> 2, q4 = lane & 3;
    const int wm   = wid & 1;    // 0..1 -> 64-row strip
    const int wn   = wid >> 1;   // 0..3 -> 32-col strip
    const int bm   = blockIdx.y * 128;
    const int bn   = blockIdx.x * 128;
    const int row  = t >> 2;     // 0..63 loader row (also +64)
    const int kq   = (t & 3) * 4;

    const float* Ap0 = A  + (size_t)(bm + row) * HID + kq;
    const float* Ap1 = A  + (size_t)(bm + row + 64) * HID + kq;
    const float* Bp0 = Bt + (size_t)(bn + row) * HID + kq;
    const float* Bp1 = Bt + (size_t)(bn + row + 64) * HID + kq;

    float acc[4][4][4];
#pragma unroll
    for (int mi = 0; mi < 4; mi++)
#pragma unroll
        for (int ni = 0; ni < 4; ni++)
#pragma unroll
            for (int e = 0; e < 4; e++) acc[mi][ni][e] = 0.f;

#define ST_TILE(buf, r, v)                         \
    do {                                           \
        (buf)[r][kq + 0] = tf32f((v).x);           \
        (buf)[r][kq + 1] = tf32f((v).y);           \
        (buf)[r][kq + 2] = tf32f((v).z);           \
        (buf)[r][kq + 3] = tf32f((v).w);           \
    } while (0)

    {
        float4 a0 = *(const float4*)Ap0;
        float4 a1 = *(const float4*)Ap1;
        float4 b0 = *(const float4*)Bp0;
        float4 b1 = *(const float4*)Bp1;
        ST_TILE(As[0], row, a0);
        ST_TILE(As[0], row + 64, a1);
        ST_TILE(Bs[0], row, b0);
        ST_TILE(Bs[0], row + 64, b1);
    }
    __syncthreads();

    const int NT = HID / 16;   // 64
    for (int k = 0; k < NT; k++) {
        const int cur = k & 1, nxt = cur ^ 1;
        float4 a0, a1, b0, b1;
        const bool more = (k + 1) < NT;
        if (more) {
            const int ko = (k + 1) * 16;
            a0 = *(const float4*)(Ap0 + ko);
            a1 = *(const float4*)(Ap1 + ko);
            b0 = *(const float4*)(Bp0 + ko);
            b1 = *(const float4*)(Bp1 + ko);
        }

#pragma unroll
        for (int kf = 0; kf < 2; kf++) {
            uint32_t af[4][4], bf[4][2];
#pragma unroll
            for (int mi = 0; mi < 4; mi++) {
                const float* p0 = &As[cur][wm * 64 + mi * 16 + gid][kf * 8 + q4];
                const float* p1 = &As[cur][wm * 64 + mi * 16 + gid + 8][kf * 8 + q4];
                af[mi][0] = __float_as_uint(p0[0]);
                af[mi][1] = __float_as_uint(p1[0]);
                af[mi][2] = __float_as_uint(p0[4]);
                af[mi][3] = __float_as_uint(p1[4]);
            }
#pragma unroll
            for (int ni = 0; ni < 4; ni++) {
                const float* p = &Bs[cur][wn * 32 + ni * 8 + gid][kf * 8 + q4];
                bf[ni][0] = __float_as_uint(p[0]);
                bf[ni][1] = __float_as_uint(p[4]);
            }
#pragma unroll
            for (int mi = 0; mi < 4; mi++)
#pragma unroll
                for (int ni = 0; ni < 4; ni++)
                    mma_tf32(acc[mi][ni], af[mi], bf[ni]);
        }

        if (more) {
            ST_TILE(As[nxt], row, a0);
            ST_TILE(As[nxt], row + 64, a1);
            ST_TILE(Bs[nxt], row, b0);
            ST_TILE(Bs[nxt], row + 64, b1);
        }
        __syncthreads();
    }
#undef ST_TILE

    // Epilogue: acc (mi,ni): c0 (grow=gid, col=2q4), c1 col+1, c2 grow+8
#pragma unroll
    for (int mi = 0; mi < 4; mi++) {
        const int r0 = bm + wm * 64 + mi * 16 + gid;
#pragma unroll
        for (int ni = 0; ni < 4; ni++) {
            const int col = bn + wn * 32 + ni * 8 + 2 * q4;
            *(float2*)(C + (size_t)r0 * ldc + col) =
                make_float2(acc[mi][ni][0], acc[mi][ni][1]);
            *(float2*)(C + (size_t)(r0 + 8) * ldc + col) =
                make_float2(acc[mi][ni][2], acc[mi][ni][3]);
        }
    }
}

// ---------------------------------------------------------------------------
// RoPE in-place on the fused QKV tensor (Q and K halves).
// ---------------------------------------------------------------------------
__global__ __launch_bounds__(256) void rope_kernel(float* __restrict__ P)
{
    int idx = blockIdx.x * blockDim.x + threadIdx.x;
    int j   = idx & 31;
    int h   = (idx >> 5) & 31;
    int row = idx >> 10;
    int s   = row & (SS - 1);

    float inv = expf(-(float)j * (9.210340371976184f / 32.0f));
    float ang = (float)s * inv;
    float sn, cs;
    sincosf(ang, &sn, &cs);

    long base = (long)row * QKVW + h * HD + j;
    float x1 = P[base];
    float x2 = P[base + 32];
    P[base]      = x1 * cs - x2 * sn;
    P[base + 32] = x2 * cs + x1 * sn;
}

// ---------------------------------------------------------------------------
// Flash attention on mma.sync tf32 (m16n8k8) — unchanged from round 6.
// ---------------------------------------------------------------------------
#define FPAD 68

__global__ __launch_bounds__(256, 2) void flashmma_kernel(
    const float* __restrict__ QKV, float* __restrict__ AO,
    const int* __restrict__ seq_lens)
{
    extern __shared__ float sm[];
    float* Ps = sm;                  // [128][FPAD]
    float* Ks = Ps + 128 * FPAD;     // [64][FPAD]
    float* Vs = Ks + 64 * FPAD;      // [64][FPAD]

    const int bx = blockIdx.x, h = blockIdx.y, b = blockIdx.z;
    const int sl = __ldg(&seq_lens[b]);
    const int q0 = bx * 128;
    const int t  = threadIdx.x;
    const int wid = t >> 5, lane = t & 31;
    const int gid = lane >> 2, q4 = lane & 3;
    const int wr  = wid * 16;

    const long qkv_base = (long)b * SS * QKVW + (long)h * HD;
    const long ao_base  = (long)b * SS * HID  + (long)h * HD;

    if (q0 >= sl) {
        for (int lin = t; lin < 128 * 16; lin += 256) {
            int r = lin >> 4, c4 = (lin & 15) * 4;
            *(float4*)(AO + ao_base + (long)(q0 + r) * HID + c4) =
                make_float4(0.f, 0.f, 0.f, 0.f);
        }
        return;
    }

    for (int lin = t; lin < 128 * 16; lin += 256) {
        int r = lin >> 4, c4 = (lin & 15) * 4;
        float4 v = *(const float4*)(QKV + qkv_base + (long)(q0 + r) * QKVW + c4);
        float* d = &Ps[r * FPAD + c4];
        d[0] = tf32f(v.x * SCALE); d[1] = tf32f(v.y * SCALE);
        d[2] = tf32f(v.z * SCALE); d[3] = tf32f(v.w * SCALE);
    }
    __syncthreads();

    uint32_t qa[8][4];
#pragma unroll
    for (int kf = 0; kf < 8; kf++) {
        const float* p0 = &Ps[(wr + gid) * FPAD + kf * 8 + q4];
        const float* p1 = &Ps[(wr + gid + 8) * FPAD + kf * 8 + q4];
        qa[kf][0] = __float_as_uint(p0[0]);
        qa[kf][1] = __float_as_uint(p1[0]);
        qa[kf][2] = __float_as_uint(p0[4]);
        qa[kf][3] = __float_as_uint(p1[4]);
    }

    float ofr[8][4];
#pragma unroll
    for (int nf = 0; nf < 8; nf++)
#pragma unroll
        for (int e = 0; e < 4; e++) ofr[nf][e] = 0.f;
    float m0 = -1e30f, m1 = -1e30f, l0 = 0.f, l1 = 0.f;

    const int r0g = q0 + wr + gid;
    const int r1g = r0g + 8;

    const int n_kt = min(2 * bx + 2, (sl + 63) >> 6);
    for (int kt = 0; kt < n_kt; kt++) {
        const int k0 = kt * 64;
        __syncthreads();
        for (int lin = t; lin < 64 * 16; lin += 256) {
            int r = lin >> 4, c4 = (lin & 15) * 4;
            long off = qkv_base + (long)(k0 + r) * QKVW + c4;
            float4 kv = *(const float4*)(QKV + off + HID);
            float4 vv = *(const float4*)(QKV + off + 2 * HID);
            float* dk = &Ks[r * FPAD + c4];
            dk[0] = tf32f(kv.x); dk[1] = tf32f(kv.y);
            dk[2] = tf32f(kv.z); dk[3] = tf32f(kv.w);
            float* dv = &Vs[r * FPAD + c4];
            dv[0] = tf32f(vv.x); dv[1] = tf32f(vv.y);
            dv[2] = tf32f(vv.z); dv[3] = tf32f(vv.w);
        }
        __syncthreads();

        float sfr[8][4];
#pragma unroll
        for (int nf = 0; nf < 8; nf++)
#pragma unroll
            for (int e = 0; e < 4; e++) sfr[nf][e] = 0.f;

#pragma unroll
        for (int kf = 0; kf < 8; kf++) {
#pragma unroll
            for (int nf = 0; nf < 8; nf++) {
                uint32_t bb[2];
                const float* kp = &Ks[(nf * 8 + gid) * FPAD + kf * 8 + q4];
                bb[0] = __float_as_uint(kp[0]);
                bb[1] = __float_as_uint(kp[4]);
                mma_tf32(sfr[nf], qa[kf], bb);
            }
        }

        if (k0 + 63 > q0 + wr) {
#pragma unroll
            for (int nf = 0; nf < 8; nf++) {
                int c0 = k0 + nf * 8 + 2 * q4, c1 = c0 + 1;
                if (c0 > r0g) sfr[nf][0] = -1e30f;
                if (c1 > r0g) sfr[nf][1] = -1e30f;
                if (c0 > r1g) sfr[nf][2] = -1e30f;
                if (c1 > r1g) sfr[nf][3] = -1e30f;
            }
        }

        float tm0 = -1e30f, tm1 = -1e30f;
#pragma unroll
        for (int nf = 0; nf < 8; nf++) {
            tm0 = fmaxf(tm0, fmaxf(sfr[nf][0], sfr[nf][1]));
            tm1 = fmaxf(tm1, fmaxf(sfr[nf][2], sfr[nf][3]));
        }
        tm0 = fmaxf(tm0, __shfl_xor_sync(0xffffffffu, tm0, 1));
        tm0 = fmaxf(tm0, __shfl_xor_sync(0xffffffffu, tm0, 2));
        tm1 = fmaxf(tm1, __shfl_xor_sync(0xffffffffu, tm1, 1));
        tm1 = fmaxf(tm1, __shfl_xor_sync(0xffffffffu, tm1, 2));

        float mn0 = fmaxf(m0, tm0), mn1 = fmaxf(m1, tm1);
        float corr0 = __expf(m0 - mn0), corr1 = __expf(m1 - mn1);
        m0 = mn0; m1 = mn1;

        float s0 = 0.f, s1 = 0.f;
#pragma unroll
        for (int nf = 0; nf < 8; nf++) {
            float p0 = __expf(sfr[nf][0] - mn0);
            float p1 = __expf(sfr[nf][1] - mn0);
            float p2 = __expf(sfr[nf][2] - mn1);
            float p3 = __expf(sfr[nf][3] - mn1);
            s0 += p0 + p1; s1 += p2 + p3;
            *(float2*)&Ps[(wr + gid) * FPAD + nf * 8 + 2 * q4] =
                make_float2(tf32f(p0), tf32f(p1));
            *(float2*)&Ps[(wr + gid + 8) * FPAD + nf * 8 + 2 * q4] =
                make_float2(tf32f(p2), tf32f(p3));
        }
        s0 += __shfl_xor_sync(0xffffffffu, s0, 1);
        s0 += __shfl_xor_sync(0xffffffffu, s0, 2);
        s1 += __shfl_xor_sync(0xffffffffu, s1, 1);
        s1 += __shfl_xor_sync(0xffffffffu, s1, 2);
        l0 = l0 * corr0 + s0;
        l1 = l1 * corr1 + s1;

#pragma unroll
        for (int nf = 0; nf < 8; nf++) {
            ofr[nf][0] *= corr0; ofr[nf][1] *= corr0;
            ofr[nf][2] *= corr1; ofr[nf][3] *= corr1;
        }
        __syncwarp();

#pragma unroll
        for (int kf = 0; kf < 8; kf++) {
            uint32_t pa[4];
            const float* pp0 = &Ps[(wr + gid) * FPAD + kf * 8 + q4];
            const float* pp1 = &Ps[(wr + gid + 8) * FPAD + kf * 8 + q4];
            pa[0] = __float_as_uint(pp0[0]);
            pa[1] = __float_as_uint(pp1[0]);
            pa[2] = __float_as_uint(pp0[4]);
            pa[3] = __float_as_uint(pp1[4]);
#pragma unroll
            for (int nf = 0; nf < 8; nf++) {
                uint32_t bb[2];
                const float* vp0 = &Vs[(kf * 8 + q4) * FPAD + nf * 8 + gid];
                const float* vp1 = &Vs[(kf * 8 + q4 + 4) * FPAD + nf * 8 + gid];
                bb[0] = __float_as_uint(vp0[0]);
                bb[1] = __float_as_uint(vp1[0]);
                mma_tf32(ofr[nf], pa, bb);
            }
        }
    }

    const float inv0 = (r0g < sl) ? (1.f / l0) : 0.f;
    const float inv1 = (r1g < sl) ? (1.f / l1) : 0.f;
#pragma unroll
    for (int nf = 0; nf < 8; nf++) {
        *(float2*)(AO + ao_base + (long)r0g * HID + nf * 8 + 2 * q4) =
            make_float2(ofr[nf][0] * inv0, ofr[nf][1] * inv0);
        *(float2*)(AO + ao_base + (long)r1g * HID + nf * 8 + 2 * q4) =
            make_float2(ofr[nf][2] * inv1, ofr[nf][3] * inv1);
    }
}

// ---------------------------------------------------------------------------
extern "C" void kernel_launch(void* const* d_in, const int* in_sizes, int n_in,
                              void* d_out, int out_size)
{
    (void)in_sizes; (void)n_in; (void)out_size;
    const float* x  = (const float*)d_in[0];
    const float* Wq = (const float*)d_in[1];
    const float* Wk = (const float*)d_in[2];
    const float* Wv = (const float*)d_in[3];
    const float* Wo = (const float*)d_in[4];
    const int*   sl = (const int*)d_in[5];
    float* out = (float*)d_out;

    float *QKV, *AO, *Wt;
    cudaGetSymbolAddress((void**)&QKV, g_QKV);
    cudaGetSymbolAddress((void**)&AO,  g_AO);
    cudaGetSymbolAddress((void**)&Wt,  g_Wt);

    const int FLASH_SMEM = (128 + 64 + 64) * FPAD * (int)sizeof(float);  // 69632
    cudaFuncSetAttribute(flashmma_kernel,
                         cudaFuncAttributeMaxDynamicSharedMemorySize, FLASH_SMEM);

    transpose_kernel<<<dim3(32, 32, 4), 256>>>(Wq, Wk, Wv, Wo);

    // Fused QKV GEMM: [8192,1024] @ [3072,1024]^T -> [8192,3072]
    rgemm_kernel<<<dim3(QKVW / 128, ROWS / 128), 256>>>(x, Wt, QKV, QKVW);

    // Fused RoPE over Q and K halves
    rope_kernel<<<(ROWS * 1024) / 256, 256>>>(QKV);

    dim3 flash_grid(SS / 128, NH, BB);       // (16, 16, 4)
    flashmma_kernel<<<flash_grid, 256, FLASH_SMEM>>>(QKV, AO, sl);

    // Output projection: AO rows past seq_len are exact zeros -> out rows zero.
    rgemm_kernel<<<dim3(HID / 128, ROWS / 128), 256>>>(
        AO, Wt + 3 * (size_t)HID * HID, out, HID);
}

// round 8
// speedup vs baseline: 3.8124x; 1.4489x over previous
#include <cuda_runtime.h>
#include <cuda_fp16.h>
#include <cstdint>
#include <math.h>

#define BB   4
#define SS   2048
#define HID  1024
#define NH   16
#define HD   64
#define ROWS (BB*SS)
#define QKVW (3*HID)
#define SCALE 0.125f   // 1/sqrt(64)

// Scratch (alloc-free rule: __device__ globals)
__device__ float g_QKV[ROWS * QKVW];    // fused [rows][Q|K|V] (fp32)
__device__ float g_AO[ROWS * HID];
__device__ float g_Wt[4 * HID * HID];   // transposed weights: Wt[n][k] = W[k][n]

__device__ __forceinline__ void mma_f16(float* d, const uint32_t* a,
                                        const uint32_t* b) {
    asm volatile(
        "mma.sync.aligned.m16n8k16.row.col.f32.f16.f16.f32 "
        "{%0,%1,%2,%3}, {%4,%5,%6,%7}, {%8,%9}, {%0,%1,%2,%3};\n"
        : "+f"(d[0]), "+f"(d[1]), "+f"(d[2]), "+f"(d[3])
        : "r"(a[0]), "r"(a[1]), "r"(a[2]), "r"(a[3]), "r"(b[0]), "r"(b[1]));
}
__device__ __forceinline__ uint32_t h2u(__half2 h) {
    return *(uint32_t*)&h;
}

// ---------------------------------------------------------------------------
// Weight transpose: Wt[z][n][k] = W_z[k][n], 1024x1024 each.
// ---------------------------------------------------------------------------
__global__ __launch_bounds__(256) void transpose_kernel(
    const float* __restrict__ W0, const float* __restrict__ W1,
    const float* __restrict__ W2, const float* __restrict__ W3)
{
    __shared__ float tile[32][33];
    const int z = blockIdx.z;
    const float* W = (z == 0) ? W0 : (z == 1) ? W1 : (z == 2) ? W2 : W3;
    float* T = g_Wt + (size_t)z * HID * HID;
    const int k0 = blockIdx.x * 32, n0 = blockIdx.y * 32;
    const int tx = threadIdx.x & 31, ty = threadIdx.x >> 5;   // 32 x 8
#pragma unroll
    for (int r = 0; r < 4; r++)
        tile[ty + r * 8][tx] = W[(size_t)(k0 + ty + r * 8) * HID + n0 + tx];
    __syncthreads();
#pragma unroll
    for (int r = 0; r < 4; r++)
        T[(size_t)(n0 + ty + r * 8) * HID + k0 + tx] = tile[tx][ty + r * 8];
}

// ---------------------------------------------------------------------------
// fp16 mma.sync GEMM: C[8192, ncols] = A[8192,1024] @ Bt^T (fp32 in/out).
// Block 128x128, BK=16 double-buffered, 8 warps 2(M)x4(N), warp tile 64x32.
// Smem half rows padded to 24 halves (12 words): (12*gid+q4) mod 32 distinct
// -> conflict-free fragment gathers.
// ---------------------------------------------------------------------------
#define GPADH 24

__global__ __launch_bounds__(256, 2) void rgemm_kernel(
    const float* __restrict__ A, const float* __restrict__ Bt,
    float* __restrict__ C, int ldc)
{
    __shared__ __half As[2][128][GPADH];
    __shared__ __half Bs[2][128][GPADH];

    const int t    = threadIdx.x;
    const int wid  = t >> 5, lane = t & 31;
    const int gid  = lane >> 2, q4 = lane & 3;
    const int wm   = wid & 1;
    const int wn   = wid >> 1;
    const int bm   = blockIdx.y * 128;
    const int bn   = blockIdx.x * 128;
    const int row  = t >> 2;     // 0..63 (also +64)
    const int kq   = (t & 3) * 4;

    const float* Ap0 = A  + (size_t)(bm + row) * HID + kq;
    const float* Ap1 = A  + (size_t)(bm + row + 64) * HID + kq;
    const float* Bp0 = Bt + (size_t)(bn + row) * HID + kq;
    const float* Bp1 = Bt + (size_t)(bn + row + 64) * HID + kq;

    float acc[4][4][4];
#pragma unroll
    for (int mi = 0; mi < 4; mi++)
#pragma unroll
        for (int ni = 0; ni < 4; ni++)
#pragma unroll
            for (int e = 0; e < 4; e++) acc[mi][ni][e] = 0.f;

#define ST_TILE(buf, r, v)                                                   \
    do {                                                                     \
        uint2 u;                                                             \
        u.x = h2u(__floats2half2_rn((v).x, (v).y));                          \
        u.y = h2u(__floats2half2_rn((v).z, (v).w));                          \
        *(uint2*)&(buf)[r][kq] = u;                                          \
    } while (0)

    {
        float4 a0 = *(const float4*)Ap0;
        float4 a1 = *(const float4*)Ap1;
        float4 b0 = *(const float4*)Bp0;
        float4 b1 = *(const float4*)Bp1;
        ST_TILE(As[0], row, a0);
        ST_TILE(As[0], row + 64, a1);
        ST_TILE(Bs[0], row, b0);
        ST_TILE(Bs[0], row + 64, b1);
    }
    __syncthreads();

    const int NT = HID / 16;   // 64
    for (int k = 0; k < NT; k++) {
        const int cur = k & 1, nxt = cur ^ 1;
        float4 a0, a1, b0, b1;
        const bool more = (k + 1) < NT;
        if (more) {
            const int ko = (k + 1) * 16;
            a0 = *(const float4*)(Ap0 + ko);
            a1 = *(const float4*)(Ap1 + ko);
            b0 = *(const float4*)(Bp0 + ko);
            b1 = *(const float4*)(Bp1 + ko);
        }

        uint32_t af[4][4], bf[4][2];
#pragma unroll
        for (int mi = 0; mi < 4; mi++) {
            const __half* p0 = &As[cur][wm * 64 + mi * 16 + gid][2 * q4];
            const __half* p1 = &As[cur][wm * 64 + mi * 16 + gid + 8][2 * q4];
            af[mi][0] = *(const uint32_t*)(p0);
            af[mi][1] = *(const uint32_t*)(p1);
            af[mi][2] = *(const uint32_t*)(p0 + 8);
            af[mi][3] = *(const uint32_t*)(p1 + 8);
        }
#pragma unroll
        for (int ni = 0; ni < 4; ni++) {
            const __half* p = &Bs[cur][wn * 32 + ni * 8 + gid][2 * q4];
            bf[ni][0] = *(const uint32_t*)(p);
            bf[ni][1] = *(const uint32_t*)(p + 8);
        }
#pragma unroll
        for (int mi = 0; mi < 4; mi++)
#pragma unroll
            for (int ni = 0; ni < 4; ni++)
                mma_f16(acc[mi][ni], af[mi], bf[ni]);

        if (more) {
            ST_TILE(As[nxt], row, a0);
            ST_TILE(As[nxt], row + 64, a1);
            ST_TILE(Bs[nxt], row, b0);
            ST_TILE(Bs[nxt], row + 64, b1);
        }
        __syncthreads();
    }
#undef ST_TILE

#pragma unroll
    for (int mi = 0; mi < 4; mi++) {
        const int r0 = bm + wm * 64 + mi * 16 + gid;
#pragma unroll
        for (int ni = 0; ni < 4; ni++) {
            const int col = bn + wn * 32 + ni * 8 + 2 * q4;
            *(float2*)(C + (size_t)r0 * ldc + col) =
                make_float2(acc[mi][ni][0], acc[mi][ni][1]);
            *(float2*)(C + (size_t)(r0 + 8) * ldc + col) =
                make_float2(acc[mi][ni][2], acc[mi][ni][3]);
        }
    }
}

// ---------------------------------------------------------------------------
// RoPE in-place on the fused QKV tensor (Q and K halves), fp32.
// ---------------------------------------------------------------------------
__global__ __launch_bounds__(256) void rope_kernel(float* __restrict__ P)
{
    int idx = blockIdx.x * blockDim.x + threadIdx.x;
    int j   = idx & 31;
    int h   = (idx >> 5) & 31;
    int row = idx >> 10;
    int s   = row & (SS - 1);

    float inv = expf(-(float)j * (9.210340371976184f / 32.0f));
    float ang = (float)s * inv;
    float sn, cs;
    sincosf(ang, &sn, &cs);

    long base = (long)row * QKVW + h * HD + j;
    float x1 = P[base];
    float x2 = P[base + 32];
    P[base]      = x1 * cs - x2 * sn;
    P[base + 32] = x2 * cs + x1 * sn;
}

// ---------------------------------------------------------------------------
// Flash attention on fp16 mma.sync m16n8k16 (fp32 softmax/accum).
// BQ=128, kv tiles 64, 8 warps x 16 q-rows. Half smem rows padded to 72
// (36 words, 36 mod 32 = 4 -> conflict-free fragment gathers).
// ---------------------------------------------------------------------------
#define FPADH 72

__global__ __launch_bounds__(256, 2) void flashmma_kernel(
    const float* __restrict__ QKV, float* __restrict__ AO,
    const int* __restrict__ seq_lens)
{
    extern __shared__ __half smh[];
    __half* Ps = smh;                 // [128][FPADH]  (Q staging, then P)
    __half* Ks = Ps + 128 * FPADH;    // [64][FPADH]
    __half* Vs = Ks + 64 * FPADH;     // [64][FPADH]

    const int bx = blockIdx.x, h = blockIdx.y, b = blockIdx.z;
    const int sl = __ldg(&seq_lens[b]);
    const int q0 = bx * 128;
    const int t  = threadIdx.x;
    const int wid = t >> 5, lane = t & 31;
    const int gid = lane >> 2, q4 = lane & 3;
    const int wr  = wid * 16;

    const long qkv_base = (long)b * SS * QKVW + (long)h * HD;
    const long ao_base  = (long)b * SS * HID  + (long)h * HD;

    if (q0 >= sl) {
        for (int lin = t; lin < 128 * 16; lin += 256) {
            int r = lin >> 4, c4 = (lin & 15) * 4;
            *(float4*)(AO + ao_base + (long)(q0 + r) * HID + c4) =
                make_float4(0.f, 0.f, 0.f, 0.f);
        }
        return;
    }

    // Stage Q (pre-scaled, fp16) into Ps.
    for (int lin = t; lin < 128 * 16; lin += 256) {
        int r = lin >> 4, c4 = (lin & 15) * 4;
        float4 v = *(const float4*)(QKV + qkv_base + (long)(q0 + r) * QKVW + c4);
        uint2 u;
        u.x = h2u(__floats2half2_rn(v.x * SCALE, v.y * SCALE));
        u.y = h2u(__floats2half2_rn(v.z * SCALE, v.w * SCALE));
        *(uint2*)&Ps[r * FPADH + c4] = u;
    }
    __syncthreads();

    // Extract per-warp Q A-fragments (4 k16 steps over d=64).
    uint32_t qa[4][4];
#pragma unroll
    for (int kf = 0; kf < 4; kf++) {
        const __half* p0 = &Ps[(wr + gid) * FPADH + kf * 16 + 2 * q4];
        const __half* p1 = &Ps[(wr + gid + 8) * FPADH + kf * 16 + 2 * q4];
        qa[kf][0] = *(const uint32_t*)(p0);
        qa[kf][1] = *(const uint32_t*)(p1);
        qa[kf][2] = *(const uint32_t*)(p0 + 8);
        qa[kf][3] = *(const uint32_t*)(p1 + 8);
    }

    float ofr[8][4];
#pragma unroll
    for (int nf = 0; nf < 8; nf++)
#pragma unroll
        for (int e = 0; e < 4; e++) ofr[nf][e] = 0.f;
    float m0 = -1e30f, m1 = -1e30f, l0 = 0.f, l1 = 0.f;

    const int r0g = q0 + wr + gid;
    const int r1g = r0g + 8;

    const int n_kt = min(2 * bx + 2, (sl + 63) >> 6);
    for (int kt = 0; kt < n_kt; kt++) {
        const int k0 = kt * 64;
        __syncthreads();   // Ks/Vs free to overwrite
        for (int lin = t; lin < 64 * 16; lin += 256) {
            int r = lin >> 4, c4 = (lin & 15) * 4;
            long off = qkv_base + (long)(k0 + r) * QKVW + c4;
            float4 kv = *(const float4*)(QKV + off + HID);
            float4 vv = *(const float4*)(QKV + off + 2 * HID);
            uint2 uk, uv;
            uk.x = h2u(__floats2half2_rn(kv.x, kv.y));
            uk.y = h2u(__floats2half2_rn(kv.z, kv.w));
            uv.x = h2u(__floats2half2_rn(vv.x, vv.y));
            uv.y = h2u(__floats2half2_rn(vv.z, vv.w));
            *(uint2*)&Ks[r * FPADH + c4] = uk;
            *(uint2*)&Vs[r * FPADH + c4] = uv;
        }
        __syncthreads();

        // S = Q @ K^T
        float sfr[8][4];
#pragma unroll
        for (int nf = 0; nf < 8; nf++)
#pragma unroll
            for (int e = 0; e < 4; e++) sfr[nf][e] = 0.f;

#pragma unroll
        for (int kf = 0; kf < 4; kf++) {
#pragma unroll
            for (int nf = 0; nf < 8; nf++) {
                uint32_t bb[2];
                const __half* kp = &Ks[(nf * 8 + gid) * FPADH + kf * 16 + 2 * q4];
                bb[0] = *(const uint32_t*)(kp);
                bb[1] = *(const uint32_t*)(kp + 8);
                mma_f16(sfr[nf], qa[kf], bb);
            }
        }

        // Causal mask (diagonal-region tiles only)
        if (k0 + 63 > q0 + wr) {
#pragma unroll
            for (int nf = 0; nf < 8; nf++) {
                int c0 = k0 + nf * 8 + 2 * q4, c1 = c0 + 1;
                if (c0 > r0g) sfr[nf][0] = -1e30f;
                if (c1 > r0g) sfr[nf][1] = -1e30f;
                if (c0 > r1g) sfr[nf][2] = -1e30f;
                if (c1 > r1g) sfr[nf][3] = -1e30f;
            }
        }

        // Online softmax (quad-local rows)
        float tm0 = -1e30f, tm1 = -1e30f;
#pragma unroll
        for (int nf = 0; nf < 8; nf++) {
            tm0 = fmaxf(tm0, fmaxf(sfr[nf][0], sfr[nf][1]));
            tm1 = fmaxf(tm1, fmaxf(sfr[nf][2], sfr[nf][3]));
        }
        tm0 = fmaxf(tm0, __shfl_xor_sync(0xffffffffu, tm0, 1));
        tm0 = fmaxf(tm0, __shfl_xor_sync(0xffffffffu, tm0, 2));
        tm1 = fmaxf(tm1, __shfl_xor_sync(0xffffffffu, tm1, 1));
        tm1 = fmaxf(tm1, __shfl_xor_sync(0xffffffffu, tm1, 2));

        float mn0 = fmaxf(m0, tm0), mn1 = fmaxf(m1, tm1);
        float corr0 = __expf(m0 - mn0), corr1 = __expf(m1 - mn1);
        m0 = mn0; m1 = mn1;

        float s0 = 0.f, s1 = 0.f;
#pragma unroll
        for (int nf = 0; nf < 8; nf++) {
            float p0 = __expf(sfr[nf][0] - mn0);
            float p1 = __expf(sfr[nf][1] - mn0);
            float p2 = __expf(sfr[nf][2] - mn1);
            float p3 = __expf(sfr[nf][3] - mn1);
            s0 += p0 + p1; s1 += p2 + p3;
            *(uint32_t*)&Ps[(wr + gid) * FPADH + nf * 8 + 2 * q4] =
                h2u(__floats2half2_rn(p0, p1));
            *(uint32_t*)&Ps[(wr + gid + 8) * FPADH + nf * 8 + 2 * q4] =
                h2u(__floats2half2_rn(p2, p3));
        }
        s0 += __shfl_xor_sync(0xffffffffu, s0, 1);
        s0 += __shfl_xor_sync(0xffffffffu, s0, 2);
        s1 += __shfl_xor_sync(0xffffffffu, s1, 1);
        s1 += __shfl_xor_sync(0xffffffffu, s1, 2);
        l0 = l0 * corr0 + s0;
        l1 = l1 * corr1 + s1;

#pragma unroll
        for (int nf = 0; nf < 8; nf++) {
            ofr[nf][0] *= corr0; ofr[nf][1] *= corr0;
            ofr[nf][2] *= corr1; ofr[nf][3] *= corr1;
        }
        __syncwarp();   // P visible within warp

        // O += P @ V  (V row-major [kv][d]; B-frags via 2x b16 loads)
#pragma unroll
        for (int kf = 0; kf < 4; kf++) {
            uint32_t pa[4];
            const __half* pp0 = &Ps[(wr + gid) * FPADH + kf * 16 + 2 * q4];
            const __half* pp1 = &Ps[(wr + gid + 8) * FPADH + kf * 16 + 2 * q4];
            pa[0] = *(const uint32_t*)(pp0);
            pa[1] = *(const uint32_t*)(pp1);
            pa[2] = *(const uint32_t*)(pp0 + 8);
            pa[3] = *(const uint32_t*)(pp1 + 8);
#pragma unroll
            for (int nf = 0; nf < 8; nf++) {
                const __half* vcol = &Vs[(kf * 16 + 2 * q4) * FPADH + nf * 8 + gid];
                uint32_t lo0 = *(const uint16_t*)(vcol);
                uint32_t hi0 = *(const uint16_t*)(vcol + FPADH);
                uint32_t lo1 = *(const uint16_t*)(vcol + 8 * FPADH);
                uint32_t hi1 = *(const uint16_t*)(vcol + 9 * FPADH);
                uint32_t bb[2];
                bb[0] = lo0 | (hi0 << 16);
                bb[1] = lo1 | (hi1 << 16);
                mma_f16(ofr[nf], pa, bb);
            }
        }
    }

    const float inv0 = (r0g < sl) ? (1.f / l0) : 0.f;
    const float inv1 = (r1g < sl) ? (1.f / l1) : 0.f;
#pragma unroll
    for (int nf = 0; nf < 8; nf++) {
        *(float2*)(AO + ao_base + (long)r0g * HID + nf * 8 + 2 * q4) =
            make_float2(ofr[nf][0] * inv0, ofr[nf][1] * inv0);
        *(float2*)(AO + ao_base + (long)r1g * HID + nf * 8 + 2 * q4) =
            make_float2(ofr[nf][2] * inv1, ofr[nf][3] * inv1);
    }
}

// ---------------------------------------------------------------------------
extern "C" void kernel_launch(void* const* d_in, const int* in_sizes, int n_in,
                              void* d_out, int out_size)
{
    (void)in_sizes; (void)n_in; (void)out_size;
    const float* x  = (const float*)d_in[0];
    const float* Wq = (const float*)d_in[1];
    const float* Wk = (const float*)d_in[2];
    const float* Wv = (const float*)d_in[3];
    const float* Wo = (const float*)d_in[4];
    const int*   sl = (const int*)d_in[5];
    float* out = (float*)d_out;

    float *QKV, *AO, *Wt;
    cudaGetSymbolAddress((void**)&QKV, g_QKV);
    cudaGetSymbolAddress((void**)&AO,  g_AO);
    cudaGetSymbolAddress((void**)&Wt,  g_Wt);

    const int FLASH_SMEM = (128 + 64 + 64) * FPADH * (int)sizeof(__half); // 36864
    cudaFuncSetAttribute(flashmma_kernel,
                         cudaFuncAttributeMaxDynamicSharedMemorySize, FLASH_SMEM);

    transpose_kernel<<<dim3(32, 32, 4), 256>>>(Wq, Wk, Wv, Wo);

    // Fused QKV GEMM: [8192,1024] @ [3072,1024]^T -> [8192,3072]
    rgemm_kernel<<<dim3(QKVW / 128, ROWS / 128), 256>>>(x, Wt, QKV, QKVW);

    // Fused RoPE over Q and K halves
    rope_kernel<<<(ROWS * 1024) / 256, 256>>>(QKV);

    dim3 flash_grid(SS / 128, NH, BB);       // (16, 16, 4)
    flashmma_kernel<<<flash_grid, 256, FLASH_SMEM>>>(QKV, AO, sl);

    // Output projection: AO rows past seq_len are exact zeros -> out rows zero.
    rgemm_kernel<<<dim3(HID / 128, ROWS / 128), 256>>>(
        AO, Wt + 3 * (size_t)HID * HID, out, HID);
}

// round 9
// speedup vs baseline: 4.8516x; 1.2726x over previous
#include <cuda_runtime.h>
#include <cuda_fp16.h>
#include <cstdint>
#include <math.h>

#define BB   4
#define SS   2048
#define HID  1024
#define NH   16
#define HD   64
#define ROWS (BB*SS)
#define QKVW (3*HID)
#define SCALE 0.125f   // 1/sqrt(64)

// Scratch (alloc-free rule: __device__ globals) — all fp16 now
__device__ __half g_xh[ROWS * HID];
__device__ __half g_QKVh[ROWS * QKVW];
__device__ __half g_AOh[ROWS * HID];
__device__ __half g_Wth[4 * HID * HID];   // transposed weights (half)

__device__ __forceinline__ void mma_f16(float* d, const uint32_t* a,
                                        const uint32_t* b) {
    asm volatile(
        "mma.sync.aligned.m16n8k16.row.col.f32.f16.f16.f32 "
        "{%0,%1,%2,%3}, {%4,%5,%6,%7}, {%8,%9}, {%0,%1,%2,%3};\n"
        : "+f"(d[0]), "+f"(d[1]), "+f"(d[2]), "+f"(d[3])
        : "r"(a[0]), "r"(a[1]), "r"(a[2]), "r"(a[3]), "r"(b[0]), "r"(b[1]));
}
__device__ __forceinline__ uint32_t h2u(__half2 h) { return *(uint32_t*)&h; }
__device__ __forceinline__ uint32_t sptr(const void* p) {
    uint32_t a;
    asm("{ .reg .u64 t; cvta.to.shared.u64 t, %1; cvt.u32.u64 %0, t; }"
        : "=r"(a) : "l"(p));
    return a;
}
#define LDSM_X4(r0, r1, r2, r3, addr)                                          \
    asm volatile("ldmatrix.sync.aligned.m8n8.x4.shared.b16 {%0,%1,%2,%3}, [%4];" \
                 : "=r"(r0), "=r"(r1), "=r"(r2), "=r"(r3) : "r"(addr))
#define LDSM_X4T(r0, r1, r2, r3, addr)                                         \
    asm volatile("ldmatrix.sync.aligned.m8n8.x4.trans.shared.b16 {%0,%1,%2,%3}, [%4];" \
                 : "=r"(r0), "=r"(r1), "=r"(r2), "=r"(r3) : "r"(addr))

// ---------------------------------------------------------------------------
// x -> half
// ---------------------------------------------------------------------------
__global__ __launch_bounds__(256) void cvt_x_kernel(const float* __restrict__ x)
{
    int idx = blockIdx.x * blockDim.x + threadIdx.x;   // over float4s
    float4 v = ((const float4*)x)[idx];
    uint2 u;
    u.x = h2u(__floats2half2_rn(v.x, v.y));
    u.y = h2u(__floats2half2_rn(v.z, v.w));
    ((uint2*)g_xh)[idx] = u;
}

// ---------------------------------------------------------------------------
// Weight transpose -> half: Wt[z][n][k] = W_z[k][n]
// ---------------------------------------------------------------------------
__global__ __launch_bounds__(256) void transpose_kernel(
    const float* __restrict__ W0, const float* __restrict__ W1,
    const float* __restrict__ W2, const float* __restrict__ W3)
{
    __shared__ float tile[32][33];
    const int z = blockIdx.z;
    const float* W = (z == 0) ? W0 : (z == 1) ? W1 : (z == 2) ? W2 : W3;
    __half* T = g_Wth + (size_t)z * HID * HID;
    const int k0 = blockIdx.x * 32, n0 = blockIdx.y * 32;
    const int tx = threadIdx.x & 31, ty = threadIdx.x >> 5;
#pragma unroll
    for (int r = 0; r < 4; r++)
        tile[ty + r * 8][tx] = W[(size_t)(k0 + ty + r * 8) * HID + n0 + tx];
    __syncthreads();
#pragma unroll
    for (int r = 0; r < 4; r++)
        T[(size_t)(n0 + ty + r * 8) * HID + k0 + tx] =
            __float2half(tile[tx][ty + r * 8]);
}

// ---------------------------------------------------------------------------
// fp16 GEMM with ldmatrix: C[8192,ncols] = A[8192,1024] @ Bt^T (half inputs).
// Block 128x128, BK=32 double-buffered, 8 warps 2(M)x4(N), warp tile 64x32.
// Smem rows 40 halves (20 words): 8-row LDSM phases tile all 32 banks.
// ---------------------------------------------------------------------------
#define GP 40

template <typename OUT>
__global__ __launch_bounds__(256, 2) void rgemm_kernel(
    const __half* __restrict__ A, const __half* __restrict__ Bt,
    OUT* __restrict__ C, int ldc)
{
    __shared__ __half As[2][128][GP];
    __shared__ __half Bs[2][128][GP];

    const int t    = threadIdx.x;
    const int wid  = t >> 5, lane = t & 31;
    const int gid  = lane >> 2, q4 = lane & 3;
    const int wm   = wid & 1;
    const int wn   = wid >> 1;
    const int bm   = blockIdx.y * 128;
    const int bn   = blockIdx.x * 128;
    const int lrow = t >> 1;           // 0..127
    const int lch  = (t & 1) * 16;     // halves 0 or 16

    const __half* Ap = A  + (size_t)(bm + lrow) * HID + lch;
    const __half* Bp = Bt + (size_t)(bn + lrow) * HID + lch;

    float acc[4][4][4];
#pragma unroll
    for (int mi = 0; mi < 4; mi++)
#pragma unroll
        for (int ni = 0; ni < 4; ni++)
#pragma unroll
            for (int e = 0; e < 4; e++) acc[mi][ni][e] = 0.f;

    // Preload stage 0
    {
        uint4 a0 = *(const uint4*)(Ap);
        uint4 a1 = *(const uint4*)(Ap + 8);
        uint4 b0 = *(const uint4*)(Bp);
        uint4 b1 = *(const uint4*)(Bp + 8);
        *(uint4*)&As[0][lrow][lch] = a0;
        *(uint4*)&As[0][lrow][lch + 8] = a1;
        *(uint4*)&Bs[0][lrow][lch] = b0;
        *(uint4*)&Bs[0][lrow][lch + 8] = b1;
    }
    __syncthreads();

    // Fragment gather addresses (per warp)
    const int arow = (lane & 15), acol8 = (lane >> 4) * 8;
    const int brow = ((lane >> 4) & 1) * 8 + (lane & 7), bcol8 = ((lane >> 3) & 1) * 8;

    const int NT = HID / 32;   // 32
    for (int k = 0; k < NT; k++) {
        const int cur = k & 1, nxt = cur ^ 1;
        uint4 a0, a1, b0, b1;
        const bool more = (k + 1) < NT;
        if (more) {
            const int ko = (k + 1) * 32;
            a0 = *(const uint4*)(Ap + ko);
            a1 = *(const uint4*)(Ap + ko + 8);
            b0 = *(const uint4*)(Bp + ko);
            b1 = *(const uint4*)(Bp + ko + 8);
        }

#pragma unroll
        for (int kf = 0; kf < 2; kf++) {
            uint32_t af[4][4], bf[4][2];
#pragma unroll
            for (int mi = 0; mi < 4; mi++) {
                uint32_t ad = sptr(&As[cur][wm * 64 + mi * 16 + arow][kf * 16 + acol8]);
                LDSM_X4(af[mi][0], af[mi][1], af[mi][2], af[mi][3], ad);
            }
#pragma unroll
            for (int np = 0; np < 2; np++) {
                uint32_t bd = sptr(&Bs[cur][wn * 32 + np * 16 + brow][kf * 16 + bcol8]);
                LDSM_X4(bf[2 * np][0], bf[2 * np][1],
                        bf[2 * np + 1][0], bf[2 * np + 1][1], bd);
            }
#pragma unroll
            for (int mi = 0; mi < 4; mi++)
#pragma unroll
                for (int ni = 0; ni < 4; ni++)
                    mma_f16(acc[mi][ni], af[mi], bf[ni]);
        }

        if (more) {
            *(uint4*)&As[nxt][lrow][lch] = a0;
            *(uint4*)&As[nxt][lrow][lch + 8] = a1;
            *(uint4*)&Bs[nxt][lrow][lch] = b0;
            *(uint4*)&Bs[nxt][lrow][lch + 8] = b1;
        }
        __syncthreads();
    }

#pragma unroll
    for (int mi = 0; mi < 4; mi++) {
        const int r0 = bm + wm * 64 + mi * 16 + gid;
#pragma unroll
        for (int ni = 0; ni < 4; ni++) {
            const int col = bn + wn * 32 + ni * 8 + 2 * q4;
            if (sizeof(OUT) == 2) {
                *(uint32_t*)((__half*)C + (size_t)r0 * ldc + col) =
                    h2u(__floats2half2_rn(acc[mi][ni][0], acc[mi][ni][1]));
                *(uint32_t*)((__half*)C + (size_t)(r0 + 8) * ldc + col) =
                    h2u(__floats2half2_rn(acc[mi][ni][2], acc[mi][ni][3]));
            } else {
                *(float2*)((float*)C + (size_t)r0 * ldc + col) =
                    make_float2(acc[mi][ni][0], acc[mi][ni][1]);
                *(float2*)((float*)C + (size_t)(r0 + 8) * ldc + col) =
                    make_float2(acc[mi][ni][2], acc[mi][ni][3]);
            }
        }
    }
}

// ---------------------------------------------------------------------------
// RoPE in-place on half QKV (Q scaled by 1/sqrt(d) here). fp32 math.
// Each thread: one (row, head, j-pair) with j = 2*(idx&15).
// ---------------------------------------------------------------------------
__global__ __launch_bounds__(256) void rope_kernel(__half* __restrict__ P)
{
    int idx = blockIdx.x * blockDim.x + threadIdx.x;
    int j2  = (idx & 15) * 2;
    int h   = (idx >> 4) & 31;         // 0..15 Q heads, 16..31 K heads
    int row = idx >> 9;
    int s   = row & (SS - 1);

    float c0, s0, c1, s1;
    {
        float inv0 = expf(-(float)j2 * (9.210340371976184f / 32.0f));
        float inv1 = expf(-(float)(j2 + 1) * (9.210340371976184f / 32.0f));
        sincosf((float)s * inv0, &s0, &c0);
        sincosf((float)s * inv1, &s1, &c1);
    }

    size_t base = (size_t)row * QKVW + h * HD + j2;
    __half2 hx1 = *(__half2*)&P[base];
    __half2 hx2 = *(__half2*)&P[base + 32];
    float x1a = __low2float(hx1), x1b = __high2float(hx1);
    float x2a = __low2float(hx2), x2b = __high2float(hx2);

    float y1a = x1a * c0 - x2a * s0, y1b = x1b * c1 - x2b * s1;
    float y2a = x2a * c0 + x1a * s0, y2b = x2b * c1 + x1b * s1;
    if (h < 16) { y1a *= SCALE; y1b *= SCALE; y2a *= SCALE; y2b *= SCALE; }

    *(__half2*)&P[base]      = __floats2half2_rn(y1a, y1b);
    *(__half2*)&P[base + 32] = __floats2half2_rn(y2a, y2b);
}

// ---------------------------------------------------------------------------
// Flash attention, fp16 mma + ldmatrix. BQ=128, kv tile 64, 8 warps x 16 rows.
// Smem half rows 72 (36 words): 8-row LDSM phases tile all banks.
// ---------------------------------------------------------------------------
#define FP 72

__global__ __launch_bounds__(256, 2) void flashmma_kernel(
    const __half* __restrict__ QKV, __half* __restrict__ AO,
    const int* __restrict__ seq_lens)
{
    extern __shared__ __half smh[];
    __half* Ps = smh;                 // [128][FP]  (Q staging, then P)
    __half* Ks = Ps + 128 * FP;       // [64][FP]
    __half* Vs = Ks + 64 * FP;        // [64][FP]

    const int bx = blockIdx.x, h = blockIdx.y, b = blockIdx.z;
    const int sl = __ldg(&seq_lens[b]);
    const int q0 = bx * 128;
    const int t  = threadIdx.x;
    const int wid = t >> 5, lane = t & 31;
    const int gid = lane >> 2, q4 = lane & 3;
    const int wr  = wid * 16;

    const size_t qkv_base = (size_t)b * SS * QKVW + (size_t)h * HD;
    const size_t ao_base  = (size_t)b * SS * HID  + (size_t)h * HD;

    if (q0 >= sl) {
        for (int lin = t; lin < 128 * 8; lin += 256) {
            int r = lin >> 3, c8 = (lin & 7) * 8;
            uint4 z = make_uint4(0, 0, 0, 0);
            *(uint4*)(AO + ao_base + (size_t)(q0 + r) * HID + c8) = z;
        }
        return;
    }

    // Stage Q (already scaled in rope)
    for (int lin = t; lin < 128 * 8; lin += 256) {
        int r = lin >> 3, c8 = (lin & 7) * 8;
        *(uint4*)&Ps[r * FP + c8] =
            *(const uint4*)(QKV + qkv_base + (size_t)(q0 + r) * QKVW + c8);
    }
    __syncthreads();

    // Q A-fragments via ldmatrix.x4
    const int arow = lane & 15, acol8 = (lane >> 4) * 8;
    uint32_t qa[4][4];
#pragma unroll
    for (int kf = 0; kf < 4; kf++) {
        uint32_t ad = sptr(&Ps[(wr + arow) * FP + kf * 16 + acol8]);
        LDSM_X4(qa[kf][0], qa[kf][1], qa[kf][2], qa[kf][3], ad);
    }

    float ofr[8][4];
#pragma unroll
    for (int nf = 0; nf < 8; nf++)
#pragma unroll
        for (int e = 0; e < 4; e++) ofr[nf][e] = 0.f;
    float m0 = -1e30f, m1 = -1e30f, l0 = 0.f, l1 = 0.f;

    const int r0g = q0 + wr + gid;
    const int r1g = r0g + 8;

    // K B-frag / V B-frag ldmatrix lane addresses
    const int krow = lane & 7, kcol8 = (lane >> 3) * 8;            // K: x4 covers 2 kf
    const int vrow = lane & 15, vcol8 = ((lane >> 4) & 1) * 8;     // V: x4.trans covers 2 nf

    const int n_kt = min(2 * bx + 2, (sl + 63) >> 6);
    for (int kt = 0; kt < n_kt; kt++) {
        const int k0 = kt * 64;
        __syncthreads();   // Ks/Vs free
        for (int lin = t; lin < 64 * 8; lin += 256) {
            int r = lin >> 3, c8 = (lin & 7) * 8;
            size_t off = qkv_base + (size_t)(k0 + r) * QKVW + c8;
            *(uint4*)&Ks[r * FP + c8] = *(const uint4*)(QKV + off + HID);
            *(uint4*)&Vs[r * FP + c8] = *(const uint4*)(QKV + off + 2 * HID);
        }
        __syncthreads();

        // S = Q @ K^T
        float sfr[8][4];
#pragma unroll
        for (int nf = 0; nf < 8; nf++) {
#pragma unroll
            for (int e = 0; e < 4; e++) sfr[nf][e] = 0.f;
            uint32_t kb[4][2];
            uint32_t d0 = sptr(&Ks[(nf * 8 + krow) * FP + kcol8]);
            LDSM_X4(kb[0][0], kb[0][1], kb[1][0], kb[1][1], d0);
            uint32_t d1 = sptr(&Ks[(nf * 8 + krow) * FP + 32 + kcol8]);
            LDSM_X4(kb[2][0], kb[2][1], kb[3][0], kb[3][1], d1);
#pragma unroll
            for (int kf = 0; kf < 4; kf++)
                mma_f16(sfr[nf], qa[kf], kb[kf]);
        }

        // Causal mask (diagonal-region tiles only)
        if (k0 + 63 > q0 + wr) {
#pragma unroll
            for (int nf = 0; nf < 8; nf++) {
                int c0 = k0 + nf * 8 + 2 * q4, c1 = c0 + 1;
                if (c0 > r0g) sfr[nf][0] = -1e30f;
                if (c1 > r0g) sfr[nf][1] = -1e30f;
                if (c0 > r1g) sfr[nf][2] = -1e30f;
                if (c1 > r1g) sfr[nf][3] = -1e30f;
            }
        }

        // Online softmax
        float tm0 = -1e30f, tm1 = -1e30f;
#pragma unroll
        for (int nf = 0; nf < 8; nf++) {
            tm0 = fmaxf(tm0, fmaxf(sfr[nf][0], sfr[nf][1]));
            tm1 = fmaxf(tm1, fmaxf(sfr[nf][2], sfr[nf][3]));
        }
        tm0 = fmaxf(tm0, __shfl_xor_sync(0xffffffffu, tm0, 1));
        tm0 = fmaxf(tm0, __shfl_xor_sync(0xffffffffu, tm0, 2));
        tm1 = fmaxf(tm1, __shfl_xor_sync(0xffffffffu, tm1, 1));
        tm1 = fmaxf(tm1, __shfl_xor_sync(0xffffffffu, tm1, 2));

        float mn0 = fmaxf(m0, tm0), mn1 = fmaxf(m1, tm1);
        float corr0 = __expf(m0 - mn0), corr1 = __expf(m1 - mn1);
        m0 = mn0; m1 = mn1;

        float s0 = 0.f, s1 = 0.f;
#pragma unroll
        for (int nf = 0; nf < 8; nf++) {
            float p0 = __expf(sfr[nf][0] - mn0);
            float p1 = __expf(sfr[nf][1] - mn0);
            float p2 = __expf(sfr[nf][2] - mn1);
            float p3 = __expf(sfr[nf][3] - mn1);
            s0 += p0 + p1; s1 += p2 + p3;
            *(uint32_t*)&Ps[(wr + gid) * FP + nf * 8 + 2 * q4] =
                h2u(__floats2half2_rn(p0, p1));
            *(uint32_t*)&Ps[(wr + gid + 8) * FP + nf * 8 + 2 * q4] =
                h2u(__floats2half2_rn(p2, p3));
        }
        s0 += __shfl_xor_sync(0xffffffffu, s0, 1);
        s0 += __shfl_xor_sync(0xffffffffu, s0, 2);
        s1 += __shfl_xor_sync(0xffffffffu, s1, 1);
        s1 += __shfl_xor_sync(0xffffffffu, s1, 2);
        l0 = l0 * corr0 + s0;
        l1 = l1 * corr1 + s1;

#pragma unroll
        for (int nf = 0; nf < 8; nf++) {
            ofr[nf][0] *= corr0; ofr[nf][1] *= corr0;
            ofr[nf][2] *= corr1; ofr[nf][3] *= corr1;
        }
        __syncwarp();

        // P A-frags (own rows) then O += P @ V
        uint32_t pa[4][4];
#pragma unroll
        for (int kf = 0; kf < 4; kf++) {
            uint32_t ad = sptr(&Ps[(wr + arow) * FP + kf * 16 + acol8]);
            LDSM_X4(pa[kf][0], pa[kf][1], pa[kf][2], pa[kf][3], ad);
        }
#pragma unroll
        for (int np = 0; np < 4; np++) {
#pragma unroll
            for (int kf = 0; kf < 4; kf++) {
                uint32_t v0, v1, v2, v3;
                uint32_t vd = sptr(&Vs[(kf * 16 + vrow) * FP + np * 16 + vcol8]);
                LDSM_X4T(v0, v1, v2, v3, vd);
                uint32_t blo[2] = {v0, v1}, bhi[2] = {v2, v3};
                mma_f16(ofr[2 * np], pa[kf], blo);
                mma_f16(ofr[2 * np + 1], pa[kf], bhi);
            }
        }
    }

    const float inv0 = (r0g < sl) ? (1.f / l0) : 0.f;
    const float inv1 = (r1g < sl) ? (1.f / l1) : 0.f;
#pragma unroll
    for (int nf = 0; nf < 8; nf++) {
        *(uint32_t*)(AO + ao_base + (size_t)r0g * HID + nf * 8 + 2 * q4) =
            h2u(__floats2half2_rn(ofr[nf][0] * inv0, ofr[nf][1] * inv0));
        *(uint32_t*)(AO + ao_base + (size_t)r1g * HID + nf * 8 + 2 * q4) =
            h2u(__floats2half2_rn(ofr[nf][2] * inv1, ofr[nf][3] * inv1));
    }
}

// ---------------------------------------------------------------------------
extern "C" void kernel_launch(void* const* d_in, const int* in_sizes, int n_in,
                              void* d_out, int out_size)
{
    (void)in_sizes; (void)n_in; (void)out_size;
    const float* x  = (const float*)d_in[0];
    const float* Wq = (const float*)d_in[1];
    const float* Wk = (const float*)d_in[2];
    const float* Wv = (const float*)d_in[3];
    const float* Wo = (const float*)d_in[4];
    const int*   sl = (const int*)d_in[5];
    float* out = (float*)d_out;

    __half *xh, *QKVh, *AOh, *Wth;
    cudaGetSymbolAddress((void**)&xh,   g_xh);
    cudaGetSymbolAddress((void**)&QKVh, g_QKVh);
    cudaGetSymbolAddress((void**)&AOh,  g_AOh);
    cudaGetSymbolAddress((void**)&Wth,  g_Wth);

    const int FLASH_SMEM = (128 + 64 + 64) * FP * (int)sizeof(__half); // 36864
    cudaFuncSetAttribute(flashmma_kernel,
                         cudaFuncAttributeMaxDynamicSharedMemorySize, FLASH_SMEM);

    cvt_x_kernel<<<(ROWS * HID / 4) / 256, 256>>>(x);
    transpose_kernel<<<dim3(32, 32, 4), 256>>>(Wq, Wk, Wv, Wo);

    // Fused QKV GEMM -> half QKV
    rgemm_kernel<__half><<<dim3(QKVW / 128, ROWS / 128), 256>>>(
        xh, Wth, QKVh, QKVW);

    // RoPE (scales Q by 1/sqrt(d))
    rope_kernel<<<(ROWS * 32 * 16) / 256, 256>>>(QKVh);

    dim3 flash_grid(SS / 128, NH, BB);       // (16, 16, 4)
    flashmma_kernel<<<flash_grid, 256, FLASH_SMEM>>>(QKVh, AOh, sl);

    // Output projection (fp32 out). AO rows past seq_len are exact zeros.
    rgemm_kernel<float><<<dim3(HID / 128, ROWS / 128), 256>>>(
        AOh, Wth + 3 * (size_t)HID * HID, out, HID);
}

// round 10
// speedup vs baseline: 5.6126x; 1.1569x over previous
#include <cuda_runtime.h>
#include <cuda_fp16.h>
#include <cstdint>
#include <math.h>

#define BB   4
#define SS   2048
#define HID  1024
#define NH   16
#define HD   64
#define ROWS (BB*SS)
#define QKVW (3*HID)
#define SCALE 0.125f   // 1/sqrt(64)

// Scratch (alloc-free rule: __device__ globals) — all fp16
__device__ __half g_xh[ROWS * HID];
__device__ __half g_QKVh[ROWS * QKVW];
__device__ __half g_AOh[ROWS * HID];
__device__ __half g_Wth[4 * HID * HID];

__device__ __forceinline__ void mma_f16(float* d, const uint32_t* a,
                                        const uint32_t* b) {
    asm volatile(
        "mma.sync.aligned.m16n8k16.row.col.f32.f16.f16.f32 "
        "{%0,%1,%2,%3}, {%4,%5,%6,%7}, {%8,%9}, {%0,%1,%2,%3};\n"
        : "+f"(d[0]), "+f"(d[1]), "+f"(d[2]), "+f"(d[3])
        : "r"(a[0]), "r"(a[1]), "r"(a[2]), "r"(a[3]), "r"(b[0]), "r"(b[1]));
}
__device__ __forceinline__ uint32_t h2u(__half2 h) { return *(uint32_t*)&h; }
__device__ __forceinline__ uint32_t sptr(const void* p) {
    uint32_t a;
    asm("{ .reg .u64 t; cvta.to.shared.u64 t, %1; cvt.u32.u64 %0, t; }"
        : "=r"(a) : "l"(p));
    return a;
}
#define LDSM_X4(r0, r1, r2, r3, addr)                                          \
    asm volatile("ldmatrix.sync.aligned.m8n8.x4.shared.b16 {%0,%1,%2,%3}, [%4];" \
                 : "=r"(r0), "=r"(r1), "=r"(r2), "=r"(r3) : "r"(addr))
#define LDSM_X4T(r0, r1, r2, r3, addr)                                         \
    asm volatile("ldmatrix.sync.aligned.m8n8.x4.trans.shared.b16 {%0,%1,%2,%3}, [%4];" \
                 : "=r"(r0), "=r"(r1), "=r"(r2), "=r"(r3) : "r"(addr))
#define CP16(dst, src)                                                         \
    asm volatile("cp.async.cg.shared.global [%0], [%1], 16;"                   \
                 :: "r"(dst), "l"(src))
#define CP_COMMIT() asm volatile("cp.async.commit_group;" ::: "memory")
#define CP_WAIT(n)  asm volatile("cp.async.wait_group %0;" :: "n"(n) : "memory")

// ---------------------------------------------------------------------------
// x -> half
// ---------------------------------------------------------------------------
__global__ __launch_bounds__(256) void cvt_x_kernel(const float* __restrict__ x)
{
    int idx = blockIdx.x * blockDim.x + threadIdx.x;
    float4 v = ((const float4*)x)[idx];
    uint2 u;
    u.x = h2u(__floats2half2_rn(v.x, v.y));
    u.y = h2u(__floats2half2_rn(v.z, v.w));
    ((uint2*)g_xh)[idx] = u;
}

// ---------------------------------------------------------------------------
// Weight transpose -> half
// ---------------------------------------------------------------------------
__global__ __launch_bounds__(256) void transpose_kernel(
    const float* __restrict__ W0, const float* __restrict__ W1,
    const float* __restrict__ W2, const float* __restrict__ W3)
{
    __shared__ float tile[32][33];
    const int z = blockIdx.z;
    const float* W = (z == 0) ? W0 : (z == 1) ? W1 : (z == 2) ? W2 : W3;
    __half* T = g_Wth + (size_t)z * HID * HID;
    const int k0 = blockIdx.x * 32, n0 = blockIdx.y * 32;
    const int tx = threadIdx.x & 31, ty = threadIdx.x >> 5;
#pragma unroll
    for (int r = 0; r < 4; r++)
        tile[ty + r * 8][tx] = W[(size_t)(k0 + ty + r * 8) * HID + n0 + tx];
    __syncthreads();
#pragma unroll
    for (int r = 0; r < 4; r++)
        T[(size_t)(n0 + ty + r * 8) * HID + k0 + tx] =
            __float2half(tile[tx][ty + r * 8]);
}

// ---------------------------------------------------------------------------
// fp16 GEMM, ldmatrix + 3-stage cp.async ring. Block 128x128, BK=32.
// ---------------------------------------------------------------------------
#define GP 40

template <typename OUT>
__global__ __launch_bounds__(256, 2) void rgemm_kernel(
    const __half* __restrict__ A, const __half* __restrict__ Bt,
    OUT* __restrict__ C, int ldc)
{
    __shared__ __half As[3][128][GP];
    __shared__ __half Bs[3][128][GP];

    const int t    = threadIdx.x;
    const int wid  = t >> 5, lane = t & 31;
    const int gid  = lane >> 2, q4 = lane & 3;
    const int wm   = wid & 1;
    const int wn   = wid >> 1;
    const int bm   = blockIdx.y * 128;
    const int bn   = blockIdx.x * 128;
    const int lrow = t >> 1;           // 0..127
    const int lch  = (t & 1) * 16;     // halves 0 or 16

    const __half* Ap = A  + (size_t)(bm + lrow) * HID + lch;
    const __half* Bp = Bt + (size_t)(bn + lrow) * HID + lch;

    uint32_t sa[3], sb[3];
#pragma unroll
    for (int s = 0; s < 3; s++) {
        sa[s] = sptr(&As[s][lrow][lch]);
        sb[s] = sptr(&Bs[s][lrow][lch]);
    }

#define LD_STAGE(s, ko)                                   \
    do {                                                  \
        CP16(sa[s],      Ap + (ko));                      \
        CP16(sa[s] + 16, Ap + (ko) + 8);                  \
        CP16(sb[s],      Bp + (ko));                      \
        CP16(sb[s] + 16, Bp + (ko) + 8);                  \
    } while (0)

    float acc[4][4][4];
#pragma unroll
    for (int mi = 0; mi < 4; mi++)
#pragma unroll
        for (int ni = 0; ni < 4; ni++)
#pragma unroll
            for (int e = 0; e < 4; e++) acc[mi][ni][e] = 0.f;

    LD_STAGE(0, 0);
    CP_COMMIT();
    LD_STAGE(1, 32);
    CP_COMMIT();
    CP_WAIT(1);
    __syncthreads();

    const int arow = (lane & 15), acol8 = (lane >> 4) * 8;
    const int brow = ((lane >> 4) & 1) * 8 + (lane & 7), bcol8 = ((lane >> 3) & 1) * 8;

    const int NT = HID / 32;   // 32
    int cur = 0;
    for (int k = 0; k < NT; k++) {
        // Prefetch k+2 into stage (k+2)%3 (overwrites stage of k-1; safe: sync'd)
        if (k + 2 < NT) {
            int ps = cur + 2; if (ps >= 3) ps -= 3;
            LD_STAGE(ps, (k + 2) * 32);
        }
        CP_COMMIT();

#pragma unroll
        for (int kf = 0; kf < 2; kf++) {
            uint32_t af[4][4], bf[4][2];
#pragma unroll
            for (int mi = 0; mi < 4; mi++) {
                uint32_t ad = sptr(&As[cur][wm * 64 + mi * 16 + arow][kf * 16 + acol8]);
                LDSM_X4(af[mi][0], af[mi][1], af[mi][2], af[mi][3], ad);
            }
#pragma unroll
            for (int np = 0; np < 2; np++) {
                uint32_t bd = sptr(&Bs[cur][wn * 32 + np * 16 + brow][kf * 16 + bcol8]);
                LDSM_X4(bf[2 * np][0], bf[2 * np][1],
                        bf[2 * np + 1][0], bf[2 * np + 1][1], bd);
            }
#pragma unroll
            for (int mi = 0; mi < 4; mi++)
#pragma unroll
                for (int ni = 0; ni < 4; ni++)
                    mma_f16(acc[mi][ni], af[mi], bf[ni]);
        }

        CP_WAIT(1);        // stage k+1 resident; k+2 may still fly
        __syncthreads();
        cur++; if (cur >= 3) cur = 0;
    }
#undef LD_STAGE

#pragma unroll
    for (int mi = 0; mi < 4; mi++) {
        const int r0 = bm + wm * 64 + mi * 16 + gid;
#pragma unroll
        for (int ni = 0; ni < 4; ni++) {
            const int col = bn + wn * 32 + ni * 8 + 2 * q4;
            if (sizeof(OUT) == 2) {
                *(uint32_t*)((__half*)C + (size_t)r0 * ldc + col) =
                    h2u(__floats2half2_rn(acc[mi][ni][0], acc[mi][ni][1]));
                *(uint32_t*)((__half*)C + (size_t)(r0 + 8) * ldc + col) =
                    h2u(__floats2half2_rn(acc[mi][ni][2], acc[mi][ni][3]));
            } else {
                *(float2*)((float*)C + (size_t)r0 * ldc + col) =
                    make_float2(acc[mi][ni][0], acc[mi][ni][1]);
                *(float2*)((float*)C + (size_t)(r0 + 8) * ldc + col) =
                    make_float2(acc[mi][ni][2], acc[mi][ni][3]);
            }
        }
    }
}

// ---------------------------------------------------------------------------
// RoPE in-place on half QKV (Q scaled by 1/sqrt(d)). fp32 math.
// ---------------------------------------------------------------------------
__global__ __launch_bounds__(256) void rope_kernel(__half* __restrict__ P)
{
    int idx = blockIdx.x * blockDim.x + threadIdx.x;
    int j2  = (idx & 15) * 2;
    int h   = (idx >> 4) & 31;
    int row = idx >> 9;
    int s   = row & (SS - 1);

    float c0, s0, c1, s1;
    {
        float inv0 = expf(-(float)j2 * (9.210340371976184f / 32.0f));
        float inv1 = expf(-(float)(j2 + 1) * (9.210340371976184f / 32.0f));
        sincosf((float)s * inv0, &s0, &c0);
        sincosf((float)s * inv1, &s1, &c1);
    }

    size_t base = (size_t)row * QKVW + h * HD + j2;
    __half2 hx1 = *(__half2*)&P[base];
    __half2 hx2 = *(__half2*)&P[base + 32];
    float x1a = __low2float(hx1), x1b = __high2float(hx1);
    float x2a = __low2float(hx2), x2b = __high2float(hx2);

    float y1a = x1a * c0 - x2a * s0, y1b = x1b * c1 - x2b * s1;
    float y2a = x2a * c0 + x1a * s0, y2b = x2b * c1 + x1b * s1;
    if (h < 16) { y1a *= SCALE; y1b *= SCALE; y2a *= SCALE; y2b *= SCALE; }

    *(__half2*)&P[base]      = __floats2half2_rn(y1a, y1b);
    *(__half2*)&P[base + 32] = __floats2half2_rn(y2a, y2b);
}

// ---------------------------------------------------------------------------
// Flash attention, fp16 mma + ldmatrix + cp.async double-buffered KV.
// ---------------------------------------------------------------------------
#define FP 72

__global__ __launch_bounds__(256, 2) void flashmma_kernel(
    const __half* __restrict__ QKV, __half* __restrict__ AO,
    const int* __restrict__ seq_lens)
{
    extern __shared__ __half smh[];
    __half* Ps = smh;                      // [128][FP]
    __half* Ks = Ps + 128 * FP;            // [2][64][FP]
    __half* Vs = Ks + 2 * 64 * FP;         // [2][64][FP]

    const int bx = blockIdx.x, h = blockIdx.y, b = blockIdx.z;
    const int sl = __ldg(&seq_lens[b]);
    const int q0 = bx * 128;
    const int t  = threadIdx.x;
    const int wid = t >> 5, lane = t & 31;
    const int gid = lane >> 2, q4 = lane & 3;
    const int wr  = wid * 16;

    const size_t qkv_base = (size_t)b * SS * QKVW + (size_t)h * HD;
    const size_t ao_base  = (size_t)b * SS * HID  + (size_t)h * HD;

    if (q0 >= sl) {
        for (int lin = t; lin < 128 * 8; lin += 256) {
            int r = lin >> 3, c8 = (lin & 7) * 8;
            *(uint4*)(AO + ao_base + (size_t)(q0 + r) * HID + c8) =
                make_uint4(0, 0, 0, 0);
        }
        return;
    }

    // KV tile loader (2 x 16B per matrix per thread per tile)
    const int lr0 = t >> 2, lc0 = (t & 3) * 16;       // rows 0..63, halves 0/16/32/48
#define LD_KV(stage, k0)                                                       \
    do {                                                                       \
        size_t off = qkv_base + (size_t)((k0) + lr0) * QKVW + lc0;             \
        uint32_t dk = sptr(&Ks[(stage) * 64 * FP + lr0 * FP + lc0]);           \
        uint32_t dv = sptr(&Vs[(stage) * 64 * FP + lr0 * FP + lc0]);           \
        CP16(dk,      QKV + off + HID);                                        \
        CP16(dk + 16, QKV + off + HID + 8);                                    \
        CP16(dv,      QKV + off + 2 * HID);                                    \
        CP16(dv + 16, QKV + off + 2 * HID + 8);                                \
    } while (0)

    const int n_kt = min(2 * bx + 2, (sl + 63) >> 6);

    // Preload KV tile 0 + stage Q, all via cp.async
    LD_KV(0, 0);
    CP_COMMIT();
    for (int lin = t; lin < 128 * 8; lin += 256) {
        int r = lin >> 3, c8 = (lin & 7) * 8;
        CP16(sptr(&Ps[r * FP + c8]),
             QKV + qkv_base + (size_t)(q0 + r) * QKVW + c8);
    }
    CP_COMMIT();
    CP_WAIT(0);
    __syncthreads();

    // Q A-fragments
    const int arow = lane & 15, acol8 = (lane >> 4) * 8;
    uint32_t qa[4][4];
#pragma unroll
    for (int kf = 0; kf < 4; kf++) {
        uint32_t ad = sptr(&Ps[(wr + arow) * FP + kf * 16 + acol8]);
        LDSM_X4(qa[kf][0], qa[kf][1], qa[kf][2], qa[kf][3], ad);
    }

    float ofr[8][4];
#pragma unroll
    for (int nf = 0; nf < 8; nf++)
#pragma unroll
        for (int e = 0; e < 4; e++) ofr[nf][e] = 0.f;
    float m0 = -1e30f, m1 = -1e30f, l0 = 0.f, l1 = 0.f;

    const int r0g = q0 + wr + gid;
    const int r1g = r0g + 8;

    const int krow = lane & 7, kcol8 = (lane >> 3) * 8;
    const int vrow = lane & 15, vcol8 = ((lane >> 4) & 1) * 8;

    for (int kt = 0; kt < n_kt; kt++) {
        const int cur = kt & 1, nxt = cur ^ 1;
        const int k0 = kt * 64;

        __syncthreads();                 // all warps done with buf[nxt]
        if (kt + 1 < n_kt) LD_KV(nxt, k0 + 64);
        CP_COMMIT();
        CP_WAIT(1);                      // tile kt resident
        __syncthreads();

        const __half* Kc = Ks + cur * 64 * FP;
        const __half* Vc = Vs + cur * 64 * FP;

        // S = Q @ K^T
        float sfr[8][4];
#pragma unroll
        for (int nf = 0; nf < 8; nf++) {
#pragma unroll
            for (int e = 0; e < 4; e++) sfr[nf][e] = 0.f;
            uint32_t kb[4][2];
            uint32_t d0 = sptr(&Kc[(nf * 8 + krow) * FP + kcol8]);
            LDSM_X4(kb[0][0], kb[0][1], kb[1][0], kb[1][1], d0);
            uint32_t d1 = sptr(&Kc[(nf * 8 + krow) * FP + 32 + kcol8]);
            LDSM_X4(kb[2][0], kb[2][1], kb[3][0], kb[3][1], d1);
#pragma unroll
            for (int kf = 0; kf < 4; kf++)
                mma_f16(sfr[nf], qa[kf], kb[kf]);
        }

        if (k0 + 63 > q0 + wr) {
#pragma unroll
            for (int nf = 0; nf < 8; nf++) {
                int c0 = k0 + nf * 8 + 2 * q4, c1 = c0 + 1;
                if (c0 > r0g) sfr[nf][0] = -1e30f;
                if (c1 > r0g) sfr[nf][1] = -1e30f;
                if (c0 > r1g) sfr[nf][2] = -1e30f;
                if (c1 > r1g) sfr[nf][3] = -1e30f;
            }
        }

        float tm0 = -1e30f, tm1 = -1e30f;
#pragma unroll
        for (int nf = 0; nf < 8; nf++) {
            tm0 = fmaxf(tm0, fmaxf(sfr[nf][0], sfr[nf][1]));
            tm1 = fmaxf(tm1, fmaxf(sfr[nf][2], sfr[nf][3]));
        }
        tm0 = fmaxf(tm0, __shfl_xor_sync(0xffffffffu, tm0, 1));
        tm0 = fmaxf(tm0, __shfl_xor_sync(0xffffffffu, tm0, 2));
        tm1 = fmaxf(tm1, __shfl_xor_sync(0xffffffffu, tm1, 1));
        tm1 = fmaxf(tm1, __shfl_xor_sync(0xffffffffu, tm1, 2));

        float mn0 = fmaxf(m0, tm0), mn1 = fmaxf(m1, tm1);
        float corr0 = __expf(m0 - mn0), corr1 = __expf(m1 - mn1);
        m0 = mn0; m1 = mn1;

        float s0 = 0.f, s1 = 0.f;
#pragma unroll
        for (int nf = 0; nf < 8; nf++) {
            float p0 = __expf(sfr[nf][0] - mn0);
            float p1 = __expf(sfr[nf][1] - mn0);
            float p2 = __expf(sfr[nf][2] - mn1);
            float p3 = __expf(sfr[nf][3] - mn1);
            s0 += p0 + p1; s1 += p2 + p3;
            *(uint32_t*)&Ps[(wr + gid) * FP + nf * 8 + 2 * q4] =
                h2u(__floats2half2_rn(p0, p1));
            *(uint32_t*)&Ps[(wr + gid + 8) * FP + nf * 8 + 2 * q4] =
                h2u(__floats2half2_rn(p2, p3));
        }
        s0 += __shfl_xor_sync(0xffffffffu, s0, 1);
        s0 += __shfl_xor_sync(0xffffffffu, s0, 2);
        s1 += __shfl_xor_sync(0xffffffffu, s1, 1);
        s1 += __shfl_xor_sync(0xffffffffu, s1, 2);
        l0 = l0 * corr0 + s0;
        l1 = l1 * corr1 + s1;

#pragma unroll
        for (int nf = 0; nf < 8; nf++) {
            ofr[nf][0] *= corr0; ofr[nf][1] *= corr0;
            ofr[nf][2] *= corr1; ofr[nf][3] *= corr1;
        }
        __syncwarp();

        uint32_t pa[4][4];
#pragma unroll
        for (int kf = 0; kf < 4; kf++) {
            uint32_t ad = sptr(&Ps[(wr + arow) * FP + kf * 16 + acol8]);
            LDSM_X4(pa[kf][0], pa[kf][1], pa[kf][2], pa[kf][3], ad);
        }
#pragma unroll
        for (int np = 0; np < 4; np++) {
#pragma unroll
            for (int kf = 0; kf < 4; kf++) {
                uint32_t v0, v1, v2, v3;
                uint32_t vd = sptr(&Vc[(kf * 16 + vrow) * FP + np * 16 + vcol8]);
                LDSM_X4T(v0, v1, v2, v3, vd);
                uint32_t blo[2] = {v0, v1}, bhi[2] = {v2, v3};
                mma_f16(ofr[2 * np], pa[kf], blo);
                mma_f16(ofr[2 * np + 1], pa[kf], bhi);
            }
        }
    }
#undef LD_KV

    const float inv0 = (r0g < sl) ? (1.f / l0) : 0.f;
    const float inv1 = (r1g < sl) ? (1.f / l1) : 0.f;
#pragma unroll
    for (int nf = 0; nf < 8; nf++) {
        *(uint32_t*)(AO + ao_base + (size_t)r0g * HID + nf * 8 + 2 * q4) =
            h2u(__floats2half2_rn(ofr[nf][0] * inv0, ofr[nf][1] * inv0));
        *(uint32_t*)(AO + ao_base + (size_t)r1g * HID + nf * 8 + 2 * q4) =
            h2u(__floats2half2_rn(ofr[nf][2] * inv1, ofr[nf][3] * inv1));
    }
}

// ---------------------------------------------------------------------------
extern "C" void kernel_launch(void* const* d_in, const int* in_sizes, int n_in,
                              void* d_out, int out_size)
{
    (void)in_sizes; (void)n_in; (void)out_size;
    const float* x  = (const float*)d_in[0];
    const float* Wq = (const float*)d_in[1];
    const float* Wk = (const float*)d_in[2];
    const float* Wv = (const float*)d_in[3];
    const float* Wo = (const float*)d_in[4];
    const int*   sl = (const int*)d_in[5];
    float* out = (float*)d_out;

    __half *xh, *QKVh, *AOh, *Wth;
    cudaGetSymbolAddress((void**)&xh,   g_xh);
    cudaGetSymbolAddress((void**)&QKVh, g_QKVh);
    cudaGetSymbolAddress((void**)&AOh,  g_AOh);
    cudaGetSymbolAddress((void**)&Wth,  g_Wth);

    const int FLASH_SMEM = (128 + 4 * 64) * FP * (int)sizeof(__half); // 55296
    cudaFuncSetAttribute(flashmma_kernel,
                         cudaFuncAttributeMaxDynamicSharedMemorySize, FLASH_SMEM);

    cvt_x_kernel<<<(ROWS * HID / 4) / 256, 256>>>(x);
    transpose_kernel<<<dim3(32, 32, 4), 256>>>(Wq, Wk, Wv, Wo);

    rgemm_kernel<__half><<<dim3(QKVW / 128, ROWS / 128), 256>>>(
        xh, Wth, QKVh, QKVW);

    rope_kernel<<<(ROWS * 32 * 16) / 256, 256>>>(QKVh);

    dim3 flash_grid(SS / 128, NH, BB);
    flashmma_kernel<<<flash_grid, 256, FLASH_SMEM>>>(QKVh, AOh, sl);

    rgemm_kernel<float><<<dim3(HID / 128, ROWS / 128), 256>>>(
        AOh, Wth + 3 * (size_t)HID * HID, out, HID);
}